// round 2
// baseline (speedup 1.0000x reference)
#include <cuda_runtime.h>

// Problem constants (fixed by setup_inputs)
#define TT    2048      // sequence length (xt | x0 concat)
#define DD    1024      // model dim
#define HH    16        // heads
#define HDIM  64        // head dim
#define BB    4         // batch
#define NBH   64        // B*H
#define MROWS 8192      // B*T
#define NHALF 1024      // n = T/2

// Scratch (no cudaMalloc allowed) — q/k/v in [b*H+h][t][hd] layout, ctx in [B*T][D]
__device__ float g_q[(size_t)NBH * TT * HDIM];
__device__ float g_k[(size_t)NBH * TT * HDIM];
__device__ float g_v[(size_t)NBH * TT * HDIM];
__device__ float g_ctx[(size_t)MROWS * DD];

// ---------------------------------------------------------------------------
// SGEMM core: C[128x128] tile, BK=8, 256 threads, 8x8 microtile (strided by 16
// for conflict-free smem reads). A row-major (M x 1024), W row-major (1024 x 1024).
// ---------------------------------------------------------------------------

__global__ void __launch_bounds__(256) sgemm_qkv(
    const float* __restrict__ x,
    const float* __restrict__ Wq, const float* __restrict__ bq,
    const float* __restrict__ Wk, const float* __restrict__ bk,
    const float* __restrict__ Wv, const float* __restrict__ bv)
{
    const int z = blockIdx.z;
    const float* W    = (z == 0) ? Wq : (z == 1) ? Wk : Wv;
    const float* bias = (z == 0) ? bq : (z == 1) ? bk : bv;
    float* dst        = (z == 0) ? g_q : (z == 1) ? g_k : g_v;
    const float scale = (z == 0) ? 0.125f : 1.0f;   // hd^-0.5 = 1/8 on q

    __shared__ float As[8][128];
    __shared__ float Bs[8][128];

    const int tid = threadIdx.x;
    const int tx = tid & 15, ty = tid >> 4;
    const int bm = blockIdx.y << 7;
    const int bn = blockIdx.x << 7;

    float acc[8][8];
#pragma unroll
    for (int i = 0; i < 8; i++)
#pragma unroll
        for (int j = 0; j < 8; j++) acc[i][j] = 0.f;

    const int a_row = tid >> 1;
    const int a_k   = (tid & 1) << 2;
    const int b_k   = tid >> 5;
    const int b_n   = (tid & 31) << 2;
    const float* Ap = x + (size_t)(bm + a_row) * DD + a_k;
    const float* Wp = W + (size_t)b_k * DD + bn + b_n;

    for (int k0 = 0; k0 < DD; k0 += 8) {
        float4 av  = *(const float4*)(Ap + k0);
        float4 bv4 = *(const float4*)(Wp + (size_t)k0 * DD);
        As[a_k + 0][a_row] = av.x;
        As[a_k + 1][a_row] = av.y;
        As[a_k + 2][a_row] = av.z;
        As[a_k + 3][a_row] = av.w;
        *(float4*)&Bs[b_k][b_n] = bv4;
        __syncthreads();
#pragma unroll
        for (int kk = 0; kk < 8; kk++) {
            float a[8], b[8];
#pragma unroll
            for (int i = 0; i < 8; i++) a[i] = As[kk][ty + (i << 4)];
#pragma unroll
            for (int j = 0; j < 8; j++) b[j] = Bs[kk][tx + (j << 4)];
#pragma unroll
            for (int i = 0; i < 8; i++)
#pragma unroll
                for (int j = 0; j < 8; j++) acc[i][j] += a[i] * b[j];
        }
        __syncthreads();
    }

    // Epilogue: bias + scale, scatter into [b*H+h][t][hd] head layout
#pragma unroll
    for (int i = 0; i < 8; i++) {
        const int gm = bm + ty + (i << 4);
        const int b_ = gm >> 11;        // / 2048
        const int t_ = gm & 2047;
#pragma unroll
        for (int j = 0; j < 8; j++) {
            const int gn = bn + tx + (j << 4);
            const int head = gn >> 6, d = gn & 63;
            const float val = (acc[i][j] + bias[gn]) * scale;
            dst[(((size_t)((b_ << 4) + head)) * TT + t_) * HDIM + d] = val;
        }
    }
}

__global__ void __launch_bounds__(256) sgemm_out(
    const float* __restrict__ Wo, const float* __restrict__ bo,
    float* __restrict__ out)
{
    __shared__ float As[8][128];
    __shared__ float Bs[8][128];

    const int tid = threadIdx.x;
    const int tx = tid & 15, ty = tid >> 4;
    const int bm = blockIdx.y << 7;
    const int bn = blockIdx.x << 7;

    float acc[8][8];
#pragma unroll
    for (int i = 0; i < 8; i++)
#pragma unroll
        for (int j = 0; j < 8; j++) acc[i][j] = 0.f;

    const int a_row = tid >> 1;
    const int a_k   = (tid & 1) << 2;
    const int b_k   = tid >> 5;
    const int b_n   = (tid & 31) << 2;
    const float* Ap = g_ctx + (size_t)(bm + a_row) * DD + a_k;
    const float* Wp = Wo + (size_t)b_k * DD + bn + b_n;

    for (int k0 = 0; k0 < DD; k0 += 8) {
        float4 av  = *(const float4*)(Ap + k0);
        float4 bv4 = *(const float4*)(Wp + (size_t)k0 * DD);
        As[a_k + 0][a_row] = av.x;
        As[a_k + 1][a_row] = av.y;
        As[a_k + 2][a_row] = av.z;
        As[a_k + 3][a_row] = av.w;
        *(float4*)&Bs[b_k][b_n] = bv4;
        __syncthreads();
#pragma unroll
        for (int kk = 0; kk < 8; kk++) {
            float a[8], b[8];
#pragma unroll
            for (int i = 0; i < 8; i++) a[i] = As[kk][ty + (i << 4)];
#pragma unroll
            for (int j = 0; j < 8; j++) b[j] = Bs[kk][tx + (j << 4)];
#pragma unroll
            for (int i = 0; i < 8; i++)
#pragma unroll
                for (int j = 0; j < 8; j++) acc[i][j] += a[i] * b[j];
        }
        __syncthreads();
    }

#pragma unroll
    for (int i = 0; i < 8; i++) {
        const int gm = bm + ty + (i << 4);
#pragma unroll
        for (int j = 0; j < 8; j++) {
            const int gn = bn + tx + (j << 4);
            out[(size_t)gm * DD + gn] = acc[i][j] + bo[gn];
        }
    }
}

// ---------------------------------------------------------------------------
// BD3LM attention. One block = one (b,h) x one 64-row q-tile (32 q-tiles).
// Tile list per q-tile qt (qt0 = 64*qt):
//   xt tile (qt<16):  qt full x0 tiles; LT boundary tile at 1024+qt0; EQ diag at qt0
//   x0 tile (qt>=16): (qt-16) full x0 tiles; LE diag tile at qt0
// Masks are local:  LE: c>>2<=r>>2   LT: c>>2<r>>2   EQ: c>>2==r>>2
// ---------------------------------------------------------------------------

#define ATTN_SMEM ((3 * 64 * 65 + 64 * 64) * 4)   // 66304 bytes

__global__ void __launch_bounds__(256) attn_kernel()
{
    extern __shared__ float sm[];
    float* Qs = sm;                 // 64 x 65
    float* Ks = sm + 64 * 65;       // 64 x 65
    float* Ss = sm + 2 * 64 * 65;   // 64 x 65
    float* Vs = sm + 3 * 64 * 65;   // 64 x 64

    const int bh  = blockIdx.y;
    const int qt  = blockIdx.x;
    const int qt0 = qt << 6;
    const int tid = threadIdx.x;
    const int tx = tid & 15, ty = tid >> 4;     // phase-1 mapping
    const int row = tid >> 2, g = tid & 3;      // phase-2/3 mapping

    // Load Q tile (already scaled by 1/8)
    const float* Qg = g_q + ((size_t)bh * TT + qt0) * HDIM;
    for (int i = tid; i < 64 * 16; i += 256) {
        const int r = i >> 4, c4 = (i & 15) << 2;
        float4 v4 = *(const float4*)(Qg + r * HDIM + c4);
        float* p = &Qs[r * 65 + c4];
        p[0] = v4.x; p[1] = v4.y; p[2] = v4.z; p[3] = v4.w;
    }

    float accv[16];
#pragma unroll
    for (int i = 0; i < 16; i++) accv[i] = 0.f;
    float m = -1e30f, l = 0.f;

    const bool is_x0 = (qt >= 16);
    const int nfull  = is_x0 ? (qt - 16) : qt;
    const int ntiles = nfull + (is_x0 ? 1 : 2);

    for (int it = 0; it < ntiles; ++it) {
        int s, mode;   // mode: 0 full, 1 LE, 2 LT, 3 EQ
        if (it < nfull)        { s = 1024 + (it << 6); mode = 0; }
        else if (is_x0)        { s = qt0;              mode = 1; }
        else if (it == nfull)  { s = 1024 + qt0;       mode = 2; }
        else                   { s = qt0;              mode = 3; }

        const float* Kg = g_k + ((size_t)bh * TT + s) * HDIM;
        const float* Vg = g_v + ((size_t)bh * TT + s) * HDIM;

        __syncthreads();   // previous phase-3 done before overwriting K/V/S
        for (int i = tid; i < 64 * 16; i += 256) {
            const int r = i >> 4, c4 = (i & 15) << 2;
            float4 k4 = *(const float4*)(Kg + r * HDIM + c4);
            float* p = &Ks[r * 65 + c4];
            p[0] = k4.x; p[1] = k4.y; p[2] = k4.z; p[3] = k4.w;
            float4 v4 = *(const float4*)(Vg + r * HDIM + c4);
            *(float4*)&Vs[r * 64 + c4] = v4;
        }
        __syncthreads();

        // Phase 1: S = Q K^T  (4x4 microtile, strided by 16 -> conflict-free)
        float sc[4][4];
#pragma unroll
        for (int i = 0; i < 4; i++)
#pragma unroll
            for (int j = 0; j < 4; j++) sc[i][j] = 0.f;

#pragma unroll 4
        for (int d = 0; d < 64; d++) {
            float a[4], b[4];
#pragma unroll
            for (int i = 0; i < 4; i++) a[i] = Qs[(ty + (i << 4)) * 65 + d];
#pragma unroll
            for (int j = 0; j < 4; j++) b[j] = Ks[(tx + (j << 4)) * 65 + d];
#pragma unroll
            for (int i = 0; i < 4; i++)
#pragma unroll
                for (int j = 0; j < 4; j++) sc[i][j] += a[i] * b[j];
        }

#pragma unroll
        for (int i = 0; i < 4; i++) {
            const int r = ty + (i << 4);
            const int r2 = r >> 2;
#pragma unroll
            for (int j = 0; j < 4; j++) {
                const int c = tx + (j << 4);
                const int c2 = c >> 2;
                const bool ok = (mode == 0) ||
                                (mode == 1 && c2 <= r2) ||
                                (mode == 2 && c2 <  r2) ||
                                (mode == 3 && c2 == r2);
                Ss[r * 65 + c] = ok ? sc[i][j] : -1e30f;
            }
        }
        __syncthreads();

        // Phase 2: online softmax (4 threads per row, shfl-combine)
        const int cb = g << 4;
        float pv[16];
        float tmax = -1e30f;
#pragma unroll
        for (int kk = 0; kk < 16; kk++) {
            pv[kk] = Ss[row * 65 + cb + kk];
            tmax = fmaxf(tmax, pv[kk]);
        }
        tmax = fmaxf(tmax, __shfl_xor_sync(0xffffffffu, tmax, 1));
        tmax = fmaxf(tmax, __shfl_xor_sync(0xffffffffu, tmax, 2));
        const float mnew = fmaxf(m, tmax);
        const float resc = __expf(m - mnew);
        float lsum = 0.f;
#pragma unroll
        for (int kk = 0; kk < 16; kk++) {
            const float p = __expf(pv[kk] - mnew);
            Ss[row * 65 + cb + kk] = p;
            lsum += p;
        }
        lsum += __shfl_xor_sync(0xffffffffu, lsum, 1);
        lsum += __shfl_xor_sync(0xffffffffu, lsum, 2);
        l = l * resc + lsum;
        m = mnew;
#pragma unroll
        for (int i = 0; i < 16; i++) accv[i] *= resc;
        __syncwarp();   // P writes visible within the 4-lane row group

        // Phase 3: acc += P V   (thread owns row, 16 contiguous dims)
#pragma unroll 4
        for (int j = 0; j < 64; j++) {
            const float p = Ss[row * 65 + j];
#pragma unroll
            for (int kk = 0; kk < 4; kk++) {
                float4 vv = *(const float4*)&Vs[j * 64 + (g << 4) + (kk << 2)];
                accv[kk * 4 + 0] += p * vv.x;
                accv[kk * 4 + 1] += p * vv.y;
                accv[kk * 4 + 2] += p * vv.z;
                accv[kk * 4 + 3] += p * vv.w;
            }
        }
    }

    // Write ctx in [B*T][D] layout for the output projection
    const float inv = 1.f / l;
    const int b_ = bh >> 4, h_ = bh & 15;
    float* outp = g_ctx + ((size_t)(b_ * TT) + qt0 + row) * DD + h_ * 64 + (g << 4);
#pragma unroll
    for (int kk = 0; kk < 4; kk++) {
        float4 o;
        o.x = accv[kk * 4 + 0] * inv;
        o.y = accv[kk * 4 + 1] * inv;
        o.z = accv[kk * 4 + 2] * inv;
        o.w = accv[kk * 4 + 3] * inv;
        *(float4*)(outp + (kk << 2)) = o;
    }
}

// ---------------------------------------------------------------------------

extern "C" void kernel_launch(void* const* d_in, const int* in_sizes, int n_in,
                              void* d_out, int out_size)
{
    const float* x  = (const float*)d_in[0];
    const float* Wq = (const float*)d_in[1];
    const float* bq = (const float*)d_in[2];
    const float* Wk = (const float*)d_in[3];
    const float* bk = (const float*)d_in[4];
    const float* Wv = (const float*)d_in[5];
    const float* bv = (const float*)d_in[6];
    const float* Wo = (const float*)d_in[7];
    const float* bo = (const float*)d_in[8];
    // d_in[9] = block_size (fixed at 4; mask structure compiled in)

    sgemm_qkv<<<dim3(8, 64, 3), 256>>>(x, Wq, bq, Wk, bk, Wv, bv);

    cudaFuncSetAttribute(attn_kernel,
                         cudaFuncAttributeMaxDynamicSharedMemorySize, ATTN_SMEM);
    attn_kernel<<<dim3(32, 64), 256, ATTN_SMEM>>>();

    sgemm_out<<<dim3(8, 64), 256>>>(Wo, bo, (float*)d_out);
}

// round 3
// speedup vs baseline: 2.5063x; 2.5063x over previous
#include <cuda_runtime.h>
#include <cuda_bf16.h>

// Problem constants (fixed by setup_inputs)
#define TT    2048
#define DD    1024
#define HH    16
#define HDIM  64
#define BB    4
#define NBH   64        // B*H
#define MROWS 8192      // B*T
#define NHALF 1024

// ---------------- scratch (no cudaMalloc allowed) ----------------
__device__ float g_q[(size_t)NBH * TT * HDIM];
__device__ float g_k[(size_t)NBH * TT * HDIM];
__device__ float g_v[(size_t)NBH * TT * HDIM];
__device__ float g_ctx[(size_t)MROWS * DD];

// bf16 hi/lo decompositions (16-byte aligned for cp.async)
__device__ __align__(16) __nv_bfloat16 g_xh[(size_t)MROWS * DD];
__device__ __align__(16) __nv_bfloat16 g_xl[(size_t)MROWS * DD];
__device__ __align__(16) __nv_bfloat16 g_wTh[(size_t)4 * DD * DD];  // [z][n][k]
__device__ __align__(16) __nv_bfloat16 g_wTl[(size_t)4 * DD * DD];
__device__ __align__(16) __nv_bfloat16 g_ch[(size_t)MROWS * DD];
__device__ __align__(16) __nv_bfloat16 g_cl[(size_t)MROWS * DD];

// ---------------- PTX helpers ----------------
__device__ __forceinline__ void mma_bf16(float* c, const unsigned* a, const unsigned* b) {
    asm volatile(
        "mma.sync.aligned.m16n8k16.row.col.f32.bf16.bf16.f32 "
        "{%0,%1,%2,%3}, {%4,%5,%6,%7}, {%8,%9}, {%0,%1,%2,%3};\n"
        : "+f"(c[0]), "+f"(c[1]), "+f"(c[2]), "+f"(c[3])
        : "r"(a[0]), "r"(a[1]), "r"(a[2]), "r"(a[3]), "r"(b[0]), "r"(b[1]));
}

__device__ __forceinline__ void ldsm_x4(unsigned* r, unsigned addr) {
    asm volatile("ldmatrix.sync.aligned.m8n8.x4.shared.b16 {%0,%1,%2,%3}, [%4];\n"
                 : "=r"(r[0]), "=r"(r[1]), "=r"(r[2]), "=r"(r[3]) : "r"(addr));
}

__device__ __forceinline__ void cp16(unsigned smem, const void* g) {
    asm volatile("cp.async.ca.shared.global [%0], [%1], 16;\n" :: "r"(smem), "l"(g));
}
#define CP_COMMIT()  asm volatile("cp.async.commit_group;\n" ::: "memory")
#define CP_WAIT_1()  asm volatile("cp.async.wait_group 1;\n" ::: "memory")
#define CP_WAIT_0()  asm volatile("cp.async.wait_group 0;\n" ::: "memory")

// ---------------- decompose kernels ----------------
__device__ __forceinline__ void split_bf16(float v, __nv_bfloat16& h, __nv_bfloat16& l) {
    h = __float2bfloat16(v);
    l = __float2bfloat16(v - __bfloat162float(h));
}

// WHICH=0: x (arg in) -> g_xh/g_xl ; WHICH=1: g_ctx -> g_ch/g_cl
template<int WHICH>
__global__ void __launch_bounds__(256) decompose_vec(const float* __restrict__ in_arg) {
    const float* in = (WHICH == 0) ? in_arg : g_ctx;
    __nv_bfloat16* hi = (WHICH == 0) ? g_xh : g_ch;
    __nv_bfloat16* lo = (WHICH == 0) ? g_xl : g_cl;
    int i = blockIdx.x * 256 + threadIdx.x;            // i indexes float4
    float4 v = ((const float4*)in)[i];
    __nv_bfloat16 h0, h1, h2, h3, l0, l1, l2, l3;
    split_bf16(v.x, h0, l0); split_bf16(v.y, h1, l1);
    split_bf16(v.z, h2, l2); split_bf16(v.w, h3, l3);
    __nv_bfloat162* hp = (__nv_bfloat162*)hi;
    __nv_bfloat162* lp = (__nv_bfloat162*)lo;
    hp[2 * i]     = __nv_bfloat162{h0, h1};
    hp[2 * i + 1] = __nv_bfloat162{h2, h3};
    lp[2 * i]     = __nv_bfloat162{l0, l1};
    lp[2 * i + 1] = __nv_bfloat162{l2, l3};
}

// W [k][n] row-major  ->  WT hi/lo [n][k]  (z: 0=q 1=k 2=v 3=o)
__global__ void __launch_bounds__(256) decompose_wT(
    const float* __restrict__ Wq, const float* __restrict__ Wk,
    const float* __restrict__ Wv, const float* __restrict__ Wo)
{
    const int z = blockIdx.z;
    const float* W = (z == 0) ? Wq : (z == 1) ? Wk : (z == 2) ? Wv : Wo;
    __shared__ float tile[32][33];
    const int n0 = blockIdx.x * 32, k0 = blockIdx.y * 32;
    const int tx = threadIdx.x & 31, ty = threadIdx.x >> 5;   // 32 x 8
#pragma unroll
    for (int r = 0; r < 32; r += 8)
        tile[ty + r][tx] = W[(size_t)(k0 + ty + r) * DD + n0 + tx];
    __syncthreads();
#pragma unroll
    for (int r = 0; r < 32; r += 8) {
        float v = tile[tx][ty + r];
        __nv_bfloat16 h, l;
        split_bf16(v, h, l);
        size_t o = (size_t)z * DD * DD + (size_t)(n0 + ty + r) * DD + k0 + tx;
        g_wTh[o] = h; g_wTl[o] = l;
    }
}

// ---------------- bf16x3 tensor-core GEMM ----------------
// C tile 128x128, BK=32 (two k16 slabs), 256 threads (8 warps of 64x32),
// double-buffered cp.async. SMEM per buffer: Ah,Al,Bh,Bl each 2 slabs x 128 rows
// x 48B (16 halves data + pad for conflict-free ldmatrix). 2*48KB = 96KB dynamic.
#define ARR_SZ   12288          // one array (hi or lo): 2*128*48
#define BUF_SZ   49152          // 4 arrays
#define SLAB_SZ  6144           // 128*48

__device__ __forceinline__ void gemm_prefetch(
    unsigned sb, int buf,
    const __nv_bfloat16* __restrict__ Ah, const __nv_bfloat16* __restrict__ Al,
    const __nv_bfloat16* __restrict__ Bh, const __nv_bfloat16* __restrict__ Bl,
    int bm, int bn, int k0, int t)
{
    const unsigned base = sb + buf * BUF_SZ;
#pragma unroll
    for (int r = 0; r < 4; r++) {                 // A: 1024 x 16B
        int idx = t + 256 * r;
        int m = idx >> 3, q = idx & 7;
        int arr = q >> 2, c = q & 3;              // c: 8-half chunk within 32
        const __nv_bfloat16* g = (arr ? Al : Ah) + (size_t)(bm + m) * DD + k0 + 8 * c;
        unsigned d = base + arr * ARR_SZ + (c >> 1) * SLAB_SZ + m * 48 + (c & 1) * 16;
        cp16(d, g);
    }
#pragma unroll
    for (int r = 0; r < 4; r++) {                 // B: 1024 x 16B
        int idx = t + 256 * r;
        int n = idx >> 3, q = idx & 7;
        int arr = q >> 2, c = q & 3;
        const __nv_bfloat16* g = (arr ? Bl : Bh) + (size_t)(bn + n) * DD + k0 + 8 * c;
        unsigned d = base + 2 * ARR_SZ + arr * ARR_SZ + (c >> 1) * SLAB_SZ + n * 48 + (c & 1) * 16;
        cp16(d, g);
    }
}

// MODE 0: QKV (z selects weight/bias/dst, q scaled by 1/8, head-scatter epilogue)
// MODE 1: out projection (dst = outp, plain store)
template<int MODE>
__global__ void __launch_bounds__(256, 2) mma_gemm(
    const float* __restrict__ biasA, const float* __restrict__ biasB,
    const float* __restrict__ biasC, float* __restrict__ outp)
{
    extern __shared__ __align__(16) char dsm[];
    const unsigned sb = (unsigned)__cvta_generic_to_shared(dsm);

    const int z = (MODE == 0) ? blockIdx.z : 3;
    const __nv_bfloat16* Ah = (MODE == 0) ? g_xh : g_ch;
    const __nv_bfloat16* Al = (MODE == 0) ? g_xl : g_cl;
    const __nv_bfloat16* Bh = g_wTh + (size_t)z * DD * DD;
    const __nv_bfloat16* Bl = g_wTl + (size_t)z * DD * DD;
    const float* bias = (MODE == 0) ? ((z == 0) ? biasA : (z == 1) ? biasB : biasC) : biasA;
    float* dst = (MODE == 0) ? ((z == 0) ? g_q : (z == 1) ? g_k : g_v) : outp;
    const float scale = (MODE == 0 && z == 0) ? 0.125f : 1.0f;

    const int t = threadIdx.x;
    const int bm = blockIdx.y << 7;
    const int bn = blockIdx.x << 7;
    const int wid = t >> 5, lane = t & 31;
    const int wm = (wid & 1) << 6;       // warp m offset (0/64)
    const int wn = (wid >> 1) << 5;      // warp n offset (0/32/64/96)

    float acc[4][4][4];
#pragma unroll
    for (int i = 0; i < 4; i++)
#pragma unroll
        for (int j = 0; j < 4; j++)
#pragma unroll
            for (int r = 0; r < 4; r++) acc[i][j][r] = 0.f;

    // ldmatrix lane->address components
    const unsigned a_row_off = (unsigned)((wm + (lane & 15)) * 48 + ((lane >> 4) << 4));
    const unsigned b_row_off = (unsigned)((wn + ((lane >> 4) << 3) + (lane & 7)) * 48 +
                                          (((lane >> 3) & 1) << 4));

    gemm_prefetch(sb, 0, Ah, Al, Bh, Bl, bm, bn, 0, t);
    CP_COMMIT();

    const int NIT = DD / 32;   // 32
    for (int it = 0; it < NIT; ++it) {
        if (it + 1 < NIT) {
            gemm_prefetch(sb, (it + 1) & 1, Ah, Al, Bh, Bl, bm, bn, (it + 1) * 32, t);
            CP_COMMIT();
            CP_WAIT_1();
        } else {
            CP_WAIT_0();
        }
        __syncthreads();

        const unsigned base = sb + (it & 1) * BUF_SZ;
#pragma unroll
        for (int s = 0; s < 2; s++) {
            const unsigned bbase = base + 2 * ARR_SZ + s * SLAB_SZ + b_row_off;
            unsigned bh[8], bl[8];
            ldsm_x4(bh,     bbase);
            ldsm_x4(bh + 4, bbase + 16 * 48);
            ldsm_x4(bl,     bbase + ARR_SZ);
            ldsm_x4(bl + 4, bbase + ARR_SZ + 16 * 48);
            const unsigned abase = base + s * SLAB_SZ + a_row_off;
#pragma unroll
            for (int i = 0; i < 4; i++) {
                unsigned ah[4], al[4];
                ldsm_x4(ah, abase + i * 16 * 48);
                ldsm_x4(al, abase + i * 16 * 48 + ARR_SZ);
#pragma unroll
                for (int j = 0; j < 4; j++) {
                    mma_bf16(acc[i][j], ah, bh + 2 * j);
                    mma_bf16(acc[i][j], ah, bl + 2 * j);
                    mma_bf16(acc[i][j], al, bh + 2 * j);
                }
            }
        }
        __syncthreads();
    }

    // epilogue
    const int gg = lane >> 2, tg = lane & 3;
#pragma unroll
    for (int i = 0; i < 4; i++) {
#pragma unroll
        for (int j = 0; j < 4; j++) {
            const int row = bm + wm + 16 * i + gg;
            const int col = bn + wn + 8 * j + 2 * tg;
            float v00 = (acc[i][j][0] + bias[col])     * scale;
            float v01 = (acc[i][j][1] + bias[col + 1]) * scale;
            float v10 = (acc[i][j][2] + bias[col])     * scale;
            float v11 = (acc[i][j][3] + bias[col + 1]) * scale;
            if (MODE == 0) {
                // scatter to [b*H+h][t][hd]
                const int head = col >> 6, d = col & 63;
                const int b0_ = row >> 11, t0_ = row & 2047;
                const int b1_ = (row + 8) >> 11, t1_ = (row + 8) & 2047;
                size_t o00 = (((size_t)(b0_ * 16 + head)) * TT + t0_) * HDIM + d;
                size_t o10 = (((size_t)(b1_ * 16 + head)) * TT + t1_) * HDIM + d;
                dst[o00] = v00; dst[o00 + 1] = v01;
                dst[o10] = v10; dst[o10 + 1] = v11;
            } else {
                dst[(size_t)row * DD + col]           = v00;
                dst[(size_t)row * DD + col + 1]       = v01;
                dst[(size_t)(row + 8) * DD + col]     = v10;
                dst[(size_t)(row + 8) * DD + col + 1] = v11;
            }
        }
    }
}

// ---------------------------------------------------------------------------
// BD3LM attention (unchanged from R1 — correct, ~1.05ms; next round's target)
// ---------------------------------------------------------------------------
#define ATTN_SMEM ((3 * 64 * 65 + 64 * 64) * 4)

__global__ void __launch_bounds__(256) attn_kernel()
{
    extern __shared__ float sm[];
    float* Qs = sm;
    float* Ks = sm + 64 * 65;
    float* Ss = sm + 2 * 64 * 65;
    float* Vs = sm + 3 * 64 * 65;

    const int bh  = blockIdx.y;
    const int qt  = blockIdx.x;
    const int qt0 = qt << 6;
    const int tid = threadIdx.x;
    const int tx = tid & 15, ty = tid >> 4;
    const int row = tid >> 2, g = tid & 3;

    const float* Qg = g_q + ((size_t)bh * TT + qt0) * HDIM;
    for (int i = tid; i < 64 * 16; i += 256) {
        const int r = i >> 4, c4 = (i & 15) << 2;
        float4 v4 = *(const float4*)(Qg + r * HDIM + c4);
        float* p = &Qs[r * 65 + c4];
        p[0] = v4.x; p[1] = v4.y; p[2] = v4.z; p[3] = v4.w;
    }

    float accv[16];
#pragma unroll
    for (int i = 0; i < 16; i++) accv[i] = 0.f;
    float m = -1e30f, l = 0.f;

    const bool is_x0 = (qt >= 16);
    const int nfull  = is_x0 ? (qt - 16) : qt;
    const int ntiles = nfull + (is_x0 ? 1 : 2);

    for (int it = 0; it < ntiles; ++it) {
        int s, mode;
        if (it < nfull)        { s = 1024 + (it << 6); mode = 0; }
        else if (is_x0)        { s = qt0;              mode = 1; }
        else if (it == nfull)  { s = 1024 + qt0;       mode = 2; }
        else                   { s = qt0;              mode = 3; }

        const float* Kg = g_k + ((size_t)bh * TT + s) * HDIM;
        const float* Vg = g_v + ((size_t)bh * TT + s) * HDIM;

        __syncthreads();
        for (int i = tid; i < 64 * 16; i += 256) {
            const int r = i >> 4, c4 = (i & 15) << 2;
            float4 k4 = *(const float4*)(Kg + r * HDIM + c4);
            float* p = &Ks[r * 65 + c4];
            p[0] = k4.x; p[1] = k4.y; p[2] = k4.z; p[3] = k4.w;
            float4 v4 = *(const float4*)(Vg + r * HDIM + c4);
            *(float4*)&Vs[r * 64 + c4] = v4;
        }
        __syncthreads();

        float sc[4][4];
#pragma unroll
        for (int i = 0; i < 4; i++)
#pragma unroll
            for (int j = 0; j < 4; j++) sc[i][j] = 0.f;

#pragma unroll 4
        for (int d = 0; d < 64; d++) {
            float a[4], b[4];
#pragma unroll
            for (int i = 0; i < 4; i++) a[i] = Qs[(ty + (i << 4)) * 65 + d];
#pragma unroll
            for (int j = 0; j < 4; j++) b[j] = Ks[(tx + (j << 4)) * 65 + d];
#pragma unroll
            for (int i = 0; i < 4; i++)
#pragma unroll
                for (int j = 0; j < 4; j++) sc[i][j] += a[i] * b[j];
        }

#pragma unroll
        for (int i = 0; i < 4; i++) {
            const int r = ty + (i << 4);
            const int r2 = r >> 2;
#pragma unroll
            for (int j = 0; j < 4; j++) {
                const int c = tx + (j << 4);
                const int c2 = c >> 2;
                const bool ok = (mode == 0) ||
                                (mode == 1 && c2 <= r2) ||
                                (mode == 2 && c2 <  r2) ||
                                (mode == 3 && c2 == r2);
                Ss[r * 65 + c] = ok ? sc[i][j] : -1e30f;
            }
        }
        __syncthreads();

        const int cb = g << 4;
        float pv[16];
        float tmax = -1e30f;
#pragma unroll
        for (int kk = 0; kk < 16; kk++) {
            pv[kk] = Ss[row * 65 + cb + kk];
            tmax = fmaxf(tmax, pv[kk]);
        }
        tmax = fmaxf(tmax, __shfl_xor_sync(0xffffffffu, tmax, 1));
        tmax = fmaxf(tmax, __shfl_xor_sync(0xffffffffu, tmax, 2));
        const float mnew = fmaxf(m, tmax);
        const float resc = __expf(m - mnew);
        float lsum = 0.f;
#pragma unroll
        for (int kk = 0; kk < 16; kk++) {
            const float p = __expf(pv[kk] - mnew);
            Ss[row * 65 + cb + kk] = p;
            lsum += p;
        }
        lsum += __shfl_xor_sync(0xffffffffu, lsum, 1);
        lsum += __shfl_xor_sync(0xffffffffu, lsum, 2);
        l = l * resc + lsum;
        m = mnew;
#pragma unroll
        for (int i = 0; i < 16; i++) accv[i] *= resc;
        __syncwarp();

#pragma unroll 4
        for (int j = 0; j < 64; j++) {
            const float p = Ss[row * 65 + j];
#pragma unroll
            for (int kk = 0; kk < 4; kk++) {
                float4 vv = *(const float4*)&Vs[j * 64 + (g << 4) + (kk << 2)];
                accv[kk * 4 + 0] += p * vv.x;
                accv[kk * 4 + 1] += p * vv.y;
                accv[kk * 4 + 2] += p * vv.z;
                accv[kk * 4 + 3] += p * vv.w;
            }
        }
    }

    const float inv = 1.f / l;
    const int b_ = bh >> 4, h_ = bh & 15;
    float* outp = g_ctx + ((size_t)(b_ * TT) + qt0 + row) * DD + h_ * 64 + (g << 4);
#pragma unroll
    for (int kk = 0; kk < 4; kk++) {
        float4 o;
        o.x = accv[kk * 4 + 0] * inv;
        o.y = accv[kk * 4 + 1] * inv;
        o.z = accv[kk * 4 + 2] * inv;
        o.w = accv[kk * 4 + 3] * inv;
        *(float4*)(outp + (kk << 2)) = o;
    }
}

// ---------------------------------------------------------------------------

extern "C" void kernel_launch(void* const* d_in, const int* in_sizes, int n_in,
                              void* d_out, int out_size)
{
    const float* x  = (const float*)d_in[0];
    const float* Wq = (const float*)d_in[1];
    const float* bq = (const float*)d_in[2];
    const float* Wk = (const float*)d_in[3];
    const float* bk = (const float*)d_in[4];
    const float* Wv = (const float*)d_in[5];
    const float* bv = (const float*)d_in[6];
    const float* Wo = (const float*)d_in[7];
    const float* bo = (const float*)d_in[8];

    cudaFuncSetAttribute(mma_gemm<0>, cudaFuncAttributeMaxDynamicSharedMemorySize, 2 * BUF_SZ);
    cudaFuncSetAttribute(mma_gemm<1>, cudaFuncAttributeMaxDynamicSharedMemorySize, 2 * BUF_SZ);
    cudaFuncSetAttribute(attn_kernel, cudaFuncAttributeMaxDynamicSharedMemorySize, ATTN_SMEM);

    // 1) split x and W^T into bf16 hi/lo
    decompose_vec<0><<<(MROWS * DD / 4) / 256, 256>>>(x);
    decompose_wT<<<dim3(32, 32, 4), 256>>>(Wq, Wk, Wv, Wo);

    // 2) QKV projections on tensor cores (bf16x3)
    mma_gemm<0><<<dim3(8, 64, 3), 256, 2 * BUF_SZ>>>(bq, bk, bv, nullptr);

    // 3) mask-sparse attention
    attn_kernel<<<dim3(32, 64), 256, ATTN_SMEM>>>();

    // 4) split ctx, output projection
    decompose_vec<1><<<(MROWS * DD / 4) / 256, 256>>>(nullptr);
    mma_gemm<1><<<dim3(8, 64, 1), 256, 2 * BUF_SZ>>>(bo, nullptr, nullptr, (float*)d_out);
}

// round 4
// speedup vs baseline: 6.4847x; 2.5874x over previous
#include <cuda_runtime.h>
#include <cuda_bf16.h>

// Problem constants (fixed by setup_inputs)
#define TT    2048
#define DD    1024
#define HH    16
#define HDIM  64
#define BB    4
#define NBH   64        // B*H
#define MROWS 8192      // B*T

// ---------------- scratch (no cudaMalloc allowed) ----------------
// bf16 hi/lo decompositions (16-byte aligned for cp.async)
__device__ __align__(16) __nv_bfloat16 g_xh[(size_t)MROWS * DD];
__device__ __align__(16) __nv_bfloat16 g_xl[(size_t)MROWS * DD];
__device__ __align__(16) __nv_bfloat16 g_wTh[(size_t)4 * DD * DD];  // [z][n][k]
__device__ __align__(16) __nv_bfloat16 g_wTl[(size_t)4 * DD * DD];
// q/k: [bh][t][64], v transposed: [bh][d][t]
__device__ __align__(16) __nv_bfloat16 g_qh[(size_t)NBH * TT * HDIM];
__device__ __align__(16) __nv_bfloat16 g_ql[(size_t)NBH * TT * HDIM];
__device__ __align__(16) __nv_bfloat16 g_kh[(size_t)NBH * TT * HDIM];
__device__ __align__(16) __nv_bfloat16 g_kl[(size_t)NBH * TT * HDIM];
__device__ __align__(16) __nv_bfloat16 g_vTh[(size_t)NBH * HDIM * TT];
__device__ __align__(16) __nv_bfloat16 g_vTl[(size_t)NBH * HDIM * TT];
// attention output (GEMM A layout)
__device__ __align__(16) __nv_bfloat16 g_ch[(size_t)MROWS * DD];
__device__ __align__(16) __nv_bfloat16 g_cl[(size_t)MROWS * DD];

// ---------------- PTX helpers ----------------
__device__ __forceinline__ void mma_bf16(float* c, const unsigned* a, const unsigned* b) {
    asm volatile(
        "mma.sync.aligned.m16n8k16.row.col.f32.bf16.bf16.f32 "
        "{%0,%1,%2,%3}, {%4,%5,%6,%7}, {%8,%9}, {%0,%1,%2,%3};\n"
        : "+f"(c[0]), "+f"(c[1]), "+f"(c[2]), "+f"(c[3])
        : "r"(a[0]), "r"(a[1]), "r"(a[2]), "r"(a[3]), "r"(b[0]), "r"(b[1]));
}

__device__ __forceinline__ void ldsm_x4(unsigned* r, unsigned addr) {
    asm volatile("ldmatrix.sync.aligned.m8n8.x4.shared.b16 {%0,%1,%2,%3}, [%4];\n"
                 : "=r"(r[0]), "=r"(r[1]), "=r"(r[2]), "=r"(r[3]) : "r"(addr));
}

__device__ __forceinline__ void cp16(unsigned smem, const void* g) {
    asm volatile("cp.async.ca.shared.global [%0], [%1], 16;\n" :: "r"(smem), "l"(g));
}
#define CP_COMMIT()  asm volatile("cp.async.commit_group;\n" ::: "memory")
#define CP_WAIT_1()  asm volatile("cp.async.wait_group 1;\n" ::: "memory")
#define CP_WAIT_0()  asm volatile("cp.async.wait_group 0;\n" ::: "memory")

__device__ __forceinline__ float ex2(float x) {
    float y; asm("ex2.approx.ftz.f32 %0, %1;\n" : "=f"(y) : "f"(x)); return y;
}

__device__ __forceinline__ void split_bf16(float v, __nv_bfloat16& h, __nv_bfloat16& l) {
    h = __float2bfloat16(v);
    l = __float2bfloat16(v - __bfloat162float(h));
}

// split two floats into packed bf16x2 hi and lo (low half = first arg)
__device__ __forceinline__ void split_pack(float a, float b, unsigned& h, unsigned& l) {
    __nv_bfloat16 ha = __float2bfloat16(a), hb = __float2bfloat16(b);
    __nv_bfloat162 hh; hh.x = ha; hh.y = hb;
    __nv_bfloat162 ll;
    ll.x = __float2bfloat16(a - __bfloat162float(ha));
    ll.y = __float2bfloat16(b - __bfloat162float(hb));
    h = *(unsigned*)&hh;
    l = *(unsigned*)&ll;
}

#define QSCALE (0.125f * 1.4426950408889634f)   // hd^-0.5 * log2(e)

// ---------------- decompose kernels ----------------
__global__ void __launch_bounds__(256) decompose_x(const float* __restrict__ in) {
    int i = blockIdx.x * 256 + threadIdx.x;            // i indexes float4
    float4 v = ((const float4*)in)[i];
    __nv_bfloat16 h0, h1, h2, h3, l0, l1, l2, l3;
    split_bf16(v.x, h0, l0); split_bf16(v.y, h1, l1);
    split_bf16(v.z, h2, l2); split_bf16(v.w, h3, l3);
    __nv_bfloat162* hp = (__nv_bfloat162*)g_xh;
    __nv_bfloat162* lp = (__nv_bfloat162*)g_xl;
    __nv_bfloat162 a; a.x = h0; a.y = h1;
    __nv_bfloat162 b; b.x = h2; b.y = h3;
    __nv_bfloat162 c; c.x = l0; c.y = l1;
    __nv_bfloat162 d; d.x = l2; d.y = l3;
    hp[2 * i] = a; hp[2 * i + 1] = b;
    lp[2 * i] = c; lp[2 * i + 1] = d;
}

// W [k][n] row-major  ->  WT hi/lo [n][k]  (z: 0=q 1=k 2=v 3=o)
__global__ void __launch_bounds__(256) decompose_wT(
    const float* __restrict__ Wq, const float* __restrict__ Wk,
    const float* __restrict__ Wv, const float* __restrict__ Wo)
{
    const int z = blockIdx.z;
    const float* W = (z == 0) ? Wq : (z == 1) ? Wk : (z == 2) ? Wv : Wo;
    __shared__ float tile[32][33];
    const int n0 = blockIdx.x * 32, k0 = blockIdx.y * 32;
    const int tx = threadIdx.x & 31, ty = threadIdx.x >> 5;   // 32 x 8
#pragma unroll
    for (int r = 0; r < 32; r += 8)
        tile[ty + r][tx] = W[(size_t)(k0 + ty + r) * DD + n0 + tx];
    __syncthreads();
#pragma unroll
    for (int r = 0; r < 32; r += 8) {
        float v = tile[tx][ty + r];
        __nv_bfloat16 h, l;
        split_bf16(v, h, l);
        size_t o = (size_t)z * DD * DD + (size_t)(n0 + ty + r) * DD + k0 + tx;
        g_wTh[o] = h; g_wTl[o] = l;
    }
}

// ---------------- bf16x3 tensor-core GEMM (projections) ----------------
#define ARR_SZ   12288          // one array (hi or lo): 2*128*48
#define BUF_SZ   49152          // 4 arrays
#define SLAB_SZ  6144           // 128*48

__device__ __forceinline__ void gemm_prefetch(
    unsigned sb, int buf,
    const __nv_bfloat16* __restrict__ Ah, const __nv_bfloat16* __restrict__ Al,
    const __nv_bfloat16* __restrict__ Bh, const __nv_bfloat16* __restrict__ Bl,
    int bm, int bn, int k0, int t)
{
    const unsigned base = sb + buf * BUF_SZ;
#pragma unroll
    for (int r = 0; r < 4; r++) {                 // A: 1024 x 16B
        int idx = t + 256 * r;
        int m = idx >> 3, q = idx & 7;
        int arr = q >> 2, c = q & 3;
        const __nv_bfloat16* g = (arr ? Al : Ah) + (size_t)(bm + m) * DD + k0 + 8 * c;
        unsigned d = base + arr * ARR_SZ + (c >> 1) * SLAB_SZ + m * 48 + (c & 1) * 16;
        cp16(d, g);
    }
#pragma unroll
    for (int r = 0; r < 4; r++) {                 // B: 1024 x 16B
        int idx = t + 256 * r;
        int n = idx >> 3, q = idx & 7;
        int arr = q >> 2, c = q & 3;
        const __nv_bfloat16* g = (arr ? Bl : Bh) + (size_t)(bn + n) * DD + k0 + 8 * c;
        unsigned d = base + 2 * ARR_SZ + arr * ARR_SZ + (c >> 1) * SLAB_SZ + n * 48 + (c & 1) * 16;
        cp16(d, g);
    }
}

// MODE 0: QKV projections -> bf16 hi/lo q/k (row layout) and vT (transposed)
// MODE 1: out projection -> fp32 d_out
template<int MODE>
__global__ void __launch_bounds__(256, 2) mma_gemm(
    const float* __restrict__ biasA, const float* __restrict__ biasB,
    const float* __restrict__ biasC, float* __restrict__ outp)
{
    extern __shared__ __align__(16) char dsm[];
    const unsigned sb = (unsigned)__cvta_generic_to_shared(dsm);

    const int z = (MODE == 0) ? blockIdx.z : 3;
    const __nv_bfloat16* Ah = (MODE == 0) ? g_xh : g_ch;
    const __nv_bfloat16* Al = (MODE == 0) ? g_xl : g_cl;
    const __nv_bfloat16* Bh = g_wTh + (size_t)z * DD * DD;
    const __nv_bfloat16* Bl = g_wTl + (size_t)z * DD * DD;
    const float* bias = (MODE == 0) ? ((z == 0) ? biasA : (z == 1) ? biasB : biasC) : biasA;
    const float scale = (MODE == 0 && z == 0) ? QSCALE : 1.0f;

    const int t = threadIdx.x;
    const int bm = blockIdx.y << 7;
    const int bn = blockIdx.x << 7;
    const int wid = t >> 5, lane = t & 31;
    const int wm = (wid & 1) << 6;
    const int wn = (wid >> 1) << 5;

    float acc[4][4][4];
#pragma unroll
    for (int i = 0; i < 4; i++)
#pragma unroll
        for (int j = 0; j < 4; j++)
#pragma unroll
            for (int r = 0; r < 4; r++) acc[i][j][r] = 0.f;

    const unsigned a_row_off = (unsigned)((wm + (lane & 15)) * 48 + ((lane >> 4) << 4));
    const unsigned b_row_off = (unsigned)((wn + ((lane >> 4) << 3) + (lane & 7)) * 48 +
                                          (((lane >> 3) & 1) << 4));

    gemm_prefetch(sb, 0, Ah, Al, Bh, Bl, bm, bn, 0, t);
    CP_COMMIT();

    const int NIT = DD / 32;
    for (int it = 0; it < NIT; ++it) {
        if (it + 1 < NIT) {
            gemm_prefetch(sb, (it + 1) & 1, Ah, Al, Bh, Bl, bm, bn, (it + 1) * 32, t);
            CP_COMMIT();
            CP_WAIT_1();
        } else {
            CP_WAIT_0();
        }
        __syncthreads();

        const unsigned base = sb + (it & 1) * BUF_SZ;
#pragma unroll
        for (int s = 0; s < 2; s++) {
            const unsigned bbase = base + 2 * ARR_SZ + s * SLAB_SZ + b_row_off;
            unsigned bh[8], bl[8];
            ldsm_x4(bh,     bbase);
            ldsm_x4(bh + 4, bbase + 16 * 48);
            ldsm_x4(bl,     bbase + ARR_SZ);
            ldsm_x4(bl + 4, bbase + ARR_SZ + 16 * 48);
            const unsigned abase = base + s * SLAB_SZ + a_row_off;
#pragma unroll
            for (int i = 0; i < 4; i++) {
                unsigned ah[4], al[4];
                ldsm_x4(ah, abase + i * 16 * 48);
                ldsm_x4(al, abase + i * 16 * 48 + ARR_SZ);
#pragma unroll
                for (int j = 0; j < 4; j++) {
                    mma_bf16(acc[i][j], ah, bh + 2 * j);
                    mma_bf16(acc[i][j], ah, bl + 2 * j);
                    mma_bf16(acc[i][j], al, bh + 2 * j);
                }
            }
        }
        __syncthreads();
    }

    const int gg = lane >> 2, tg = lane & 3;
#pragma unroll
    for (int i = 0; i < 4; i++) {
#pragma unroll
        for (int j = 0; j < 4; j++) {
            const int row = bm + wm + 16 * i + gg;
            const int col = bn + wn + 8 * j + 2 * tg;
            float v00 = (acc[i][j][0] + bias[col])     * scale;
            float v01 = (acc[i][j][1] + bias[col + 1]) * scale;
            float v10 = (acc[i][j][2] + bias[col])     * scale;
            float v11 = (acc[i][j][3] + bias[col + 1]) * scale;
            if (MODE == 0) {
                const int head = col >> 6, d = col & 63;
                const int b0_ = row >> 11, t0_ = row & 2047;
                const int t1_ = (row + 8) & 2047;        // row+8 same b0_
                const int bh_ = b0_ * 16 + head;
                if (z == 2) {
                    // vT: [bh][d][t]
                    __nv_bfloat16 h00, l00, h01, l01, h10, l10, h11, l11;
                    split_bf16(v00, h00, l00); split_bf16(v01, h01, l01);
                    split_bf16(v10, h10, l10); split_bf16(v11, h11, l11);
                    size_t r0 = ((size_t)bh_ * 64 + d) * 2048;
                    size_t r1 = ((size_t)bh_ * 64 + d + 1) * 2048;
                    g_vTh[r0 + t0_] = h00; g_vTl[r0 + t0_] = l00;
                    g_vTh[r1 + t0_] = h01; g_vTl[r1 + t0_] = l01;
                    g_vTh[r0 + t1_] = h10; g_vTl[r0 + t1_] = l10;
                    g_vTh[r1 + t1_] = h11; g_vTl[r1 + t1_] = l11;
                } else {
                    __nv_bfloat16* dh = (z == 0) ? g_qh : g_kh;
                    __nv_bfloat16* dl = (z == 0) ? g_ql : g_kl;
                    unsigned p00, p00l, p10, p10l;
                    split_pack(v00, v01, p00, p00l);
                    split_pack(v10, v11, p10, p10l);
                    size_t o0 = ((size_t)bh_ * 2048 + t0_) * 64 + d;
                    size_t o1 = ((size_t)bh_ * 2048 + t1_) * 64 + d;
                    *(unsigned*)(dh + o0) = p00; *(unsigned*)(dl + o0) = p00l;
                    *(unsigned*)(dh + o1) = p10; *(unsigned*)(dl + o1) = p10l;
                }
            } else {
                outp[(size_t)row * DD + col]           = v00;
                outp[(size_t)row * DD + col + 1]       = v01;
                outp[(size_t)(row + 8) * DD + col]     = v10;
                outp[(size_t)(row + 8) * DD + col + 1] = v11;
            }
        }
    }
}

// ---------------------------------------------------------------------------
// Tensor-core BD3LM attention. Block = (bh, 64-row q-tile), 128 threads (4 warps,
// each warp m16 x n64). K tiles [kv][hd], V^T tiles [hd][kv], pitch 72 halves.
// bf16x3 for QK^T and P*V. Scores pre-scaled to log2 units (ex2 softmax).
// ---------------------------------------------------------------------------
#define AT_PITCH  144                 // bytes per row (72 halves)
#define AT_ARR    (64 * AT_PITCH)     // 9216
#define AT_BUF    (4 * AT_ARR)        // 36864 (Khi, Klo, Vhi, Vlo)
#define AT_SMEM   (2 * AT_BUF)        // 73728

__global__ void __launch_bounds__(128) attn_mma()
{
    extern __shared__ __align__(16) char dsm[];
    const unsigned sb = (unsigned)__cvta_generic_to_shared(dsm);

    const int bi = blockIdx.x;
    // heavy-first ordering: 15,31,14,30,...  (xt qt has qt+2 tiles, x0 qt-15)
    const int qt = (bi & 1) ? (31 - (bi >> 1)) : (15 - (bi >> 1));
    const int bh = blockIdx.y;
    const int qt0 = qt << 6;
    const int tid = threadIdx.x;
    const int lane = tid & 31, warp = tid >> 5;
    const int wm = warp << 4;
    const int g = lane >> 2, tq = lane & 3;

    // ---- stage Q hi/lo into smem (overlaps K buffer 0; consumed before loop) ----
#pragma unroll
    for (int i = 0; i < 8; i++) {
        int idx = tid + (i << 7);
        int arr = idx >> 9, rem = idx & 511;
        int r = rem >> 3, c = rem & 7;
        const __nv_bfloat16* src = (arr ? g_ql : g_qh) +
            ((size_t)bh * 2048 + qt0 + r) * 64 + c * 8;
        cp16(sb + arr * AT_ARR + r * AT_PITCH + c * 16, src);
    }
    CP_COMMIT();
    CP_WAIT_0();
    __syncthreads();

    unsigned qh[4][4], ql[4][4];
    const unsigned a_off = (unsigned)((wm + (lane & 15)) * AT_PITCH + ((lane >> 4) << 4));
#pragma unroll
    for (int c = 0; c < 4; c++) {
        ldsm_x4(qh[c], sb + a_off + c * 32);
        ldsm_x4(ql[c], sb + AT_ARR + a_off + c * 32);
    }
    __syncthreads();

    float o[8][4];
#pragma unroll
    for (int j = 0; j < 8; j++)
#pragma unroll
        for (int k = 0; k < 4; k++) o[j][k] = 0.f;
    float m0 = -1e30f, m1 = -1e30f, l0 = 0.f, l1 = 0.f;

    const bool is_x0 = (qt >= 16);
    const int nfull  = is_x0 ? (qt - 16) : qt;
    const int ntiles = nfull + (is_x0 ? 1 : 2);

    // tile -> (kv start, mode)  mode: 0 full, 1 LE, 2 LT, 3 EQ
    auto tile_of = [&](int it, int& s, int& mode) {
        if (it < nfull)        { s = 1024 + (it << 6); mode = 0; }
        else if (is_x0)        { s = qt0 - 1024 + 1024; mode = 1; s = qt0; }
        else if (it == nfull)  { s = 1024 + qt0;       mode = 2; }
        else                   { s = qt0;              mode = 3; }
    };

    auto prefetch = [&](int s, int buf) {
        unsigned dstb = sb + buf * AT_BUF;
#pragma unroll
        for (int i = 0; i < 16; i++) {
            int idx = tid + (i << 7);
            int arr = idx >> 9, rem = idx & 511;
            int r = rem >> 3, c = rem & 7;
            const __nv_bfloat16* src;
            if (arr == 0)      src = g_kh  + ((size_t)bh * 2048 + s + r) * 64 + c * 8;
            else if (arr == 1) src = g_kl  + ((size_t)bh * 2048 + s + r) * 64 + c * 8;
            else if (arr == 2) src = g_vTh + ((size_t)bh * 64 + r) * 2048 + s + c * 8;
            else               src = g_vTl + ((size_t)bh * 64 + r) * 2048 + s + c * 8;
            cp16(dstb + arr * AT_ARR + r * AT_PITCH + c * 16, src);
        }
    };

    {
        int s0, md0; tile_of(0, s0, md0);
        prefetch(s0, 0);
        CP_COMMIT();
    }

    const unsigned b_off = (unsigned)((((lane >> 4) << 3) + (lane & 7)) * AT_PITCH +
                                      (((lane >> 3) & 1) << 4));

    for (int it = 0; it < ntiles; ++it) {
        int s_, mode; tile_of(it, s_, mode);
        if (it + 1 < ntiles) {
            int sn, mn; tile_of(it + 1, sn, mn);
            prefetch(sn, (it + 1) & 1);
            CP_COMMIT();
            CP_WAIT_1();
        } else {
            CP_WAIT_0();
        }
        __syncthreads();

        const unsigned base = sb + (it & 1) * AT_BUF;

        // ---- S = Q K^T (bf16x3), accumulators in log2 units ----
        float sc[8][4];
#pragma unroll
        for (int j = 0; j < 8; j++)
#pragma unroll
            for (int k = 0; k < 4; k++) sc[j][k] = 0.f;

#pragma unroll
        for (int c = 0; c < 4; c++) {
#pragma unroll
            for (int p = 0; p < 4; p++) {
                unsigned kb[4], kl2[4];
                ldsm_x4(kb,  base + (p << 4) * AT_PITCH + b_off + c * 32);
                ldsm_x4(kl2, base + AT_ARR + (p << 4) * AT_PITCH + b_off + c * 32);
                mma_bf16(sc[2 * p],     qh[c], kb);
                mma_bf16(sc[2 * p],     ql[c], kb);
                mma_bf16(sc[2 * p],     qh[c], kl2);
                mma_bf16(sc[2 * p + 1], qh[c], kb + 2);
                mma_bf16(sc[2 * p + 1], ql[c], kb + 2);
                mma_bf16(sc[2 * p + 1], qh[c], kl2 + 2);
            }
        }

        // ---- mask (boundary tiles only) ----
        if (mode) {
#pragma unroll
            for (int j = 0; j < 8; j++)
#pragma unroll
                for (int k = 0; k < 4; k++) {
                    int r = wm + g + ((k >> 1) << 3);
                    int c = (j << 3) + (tq << 1) + (k & 1);
                    int r2 = r >> 2, c2 = c >> 2;
                    bool ok = (mode == 1) ? (c2 <= r2) :
                              (mode == 2) ? (c2 <  r2) : (c2 == r2);
                    if (!ok) sc[j][k] = -1e30f;
                }
        }

        // ---- online softmax (rows g / g+8; quad shfl over tq) ----
        float t0 = -1e30f, t1 = -1e30f;
#pragma unroll
        for (int j = 0; j < 8; j++) {
            t0 = fmaxf(t0, fmaxf(sc[j][0], sc[j][1]));
            t1 = fmaxf(t1, fmaxf(sc[j][2], sc[j][3]));
        }
        t0 = fmaxf(t0, __shfl_xor_sync(0xffffffffu, t0, 1));
        t0 = fmaxf(t0, __shfl_xor_sync(0xffffffffu, t0, 2));
        t1 = fmaxf(t1, __shfl_xor_sync(0xffffffffu, t1, 1));
        t1 = fmaxf(t1, __shfl_xor_sync(0xffffffffu, t1, 2));
        const float mn0 = fmaxf(m0, t0), mn1 = fmaxf(m1, t1);
        const float r0 = ex2(m0 - mn0), r1 = ex2(m1 - mn1);
        float ls0 = 0.f, ls1 = 0.f;
#pragma unroll
        for (int j = 0; j < 8; j++) {
            sc[j][0] = ex2(sc[j][0] - mn0);
            sc[j][1] = ex2(sc[j][1] - mn0);
            sc[j][2] = ex2(sc[j][2] - mn1);
            sc[j][3] = ex2(sc[j][3] - mn1);
            ls0 += sc[j][0] + sc[j][1];
            ls1 += sc[j][2] + sc[j][3];
        }
        ls0 += __shfl_xor_sync(0xffffffffu, ls0, 1);
        ls0 += __shfl_xor_sync(0xffffffffu, ls0, 2);
        ls1 += __shfl_xor_sync(0xffffffffu, ls1, 1);
        ls1 += __shfl_xor_sync(0xffffffffu, ls1, 2);
        l0 = l0 * r0 + ls0;  m0 = mn0;
        l1 = l1 * r1 + ls1;  m1 = mn1;
#pragma unroll
        for (int j = 0; j < 8; j++) {
            o[j][0] *= r0; o[j][1] *= r0;
            o[j][2] *= r1; o[j][3] *= r1;
        }

        // ---- O += P V (bf16x3; P repacked accumulator->A fragment) ----
#pragma unroll
        for (int c = 0; c < 4; c++) {
            unsigned ah[4], al[4];
            split_pack(sc[2 * c][0],     sc[2 * c][1],     ah[0], al[0]);
            split_pack(sc[2 * c][2],     sc[2 * c][3],     ah[1], al[1]);
            split_pack(sc[2 * c + 1][0], sc[2 * c + 1][1], ah[2], al[2]);
            split_pack(sc[2 * c + 1][2], sc[2 * c + 1][3], ah[3], al[3]);
#pragma unroll
            for (int p = 0; p < 4; p++) {
                unsigned vb[4], vl2[4];
                ldsm_x4(vb,  base + 2 * AT_ARR + (p << 4) * AT_PITCH + b_off + c * 32);
                ldsm_x4(vl2, base + 3 * AT_ARR + (p << 4) * AT_PITCH + b_off + c * 32);
                mma_bf16(o[2 * p],     ah, vb);
                mma_bf16(o[2 * p],     al, vb);
                mma_bf16(o[2 * p],     ah, vl2);
                mma_bf16(o[2 * p + 1], ah, vb + 2);
                mma_bf16(o[2 * p + 1], al, vb + 2);
                mma_bf16(o[2 * p + 1], ah, vl2 + 2);
            }
        }
        __syncthreads();
    }

    // ---- epilogue: normalize, split hi/lo, store ctx [B*T][D] bf16 ----
    const float inv0 = 1.f / l0, inv1 = 1.f / l1;
    const int b_ = bh >> 4, h_ = bh & 15;
    const int row0 = qt0 + wm + g;
    __nv_bfloat16* ch0 = g_ch + ((size_t)b_ * 2048 + row0) * 1024 + h_ * 64 + (tq << 1);
    __nv_bfloat16* cl0 = g_cl + ((size_t)b_ * 2048 + row0) * 1024 + h_ * 64 + (tq << 1);
#pragma unroll
    for (int j = 0; j < 8; j++) {
        unsigned ph, pl;
        split_pack(o[j][0] * inv0, o[j][1] * inv0, ph, pl);
        *(unsigned*)(ch0 + (j << 3)) = ph;
        *(unsigned*)(cl0 + (j << 3)) = pl;
        split_pack(o[j][2] * inv1, o[j][3] * inv1, ph, pl);
        *(unsigned*)(ch0 + 8 * 1024 + (j << 3)) = ph;
        *(unsigned*)(cl0 + 8 * 1024 + (j << 3)) = pl;
    }
}

// ---------------------------------------------------------------------------

extern "C" void kernel_launch(void* const* d_in, const int* in_sizes, int n_in,
                              void* d_out, int out_size)
{
    const float* x  = (const float*)d_in[0];
    const float* Wq = (const float*)d_in[1];
    const float* bq = (const float*)d_in[2];
    const float* Wk = (const float*)d_in[3];
    const float* bk = (const float*)d_in[4];
    const float* Wv = (const float*)d_in[5];
    const float* bv = (const float*)d_in[6];
    const float* Wo = (const float*)d_in[7];
    const float* bo = (const float*)d_in[8];

    cudaFuncSetAttribute(mma_gemm<0>, cudaFuncAttributeMaxDynamicSharedMemorySize, 2 * BUF_SZ);
    cudaFuncSetAttribute(mma_gemm<1>, cudaFuncAttributeMaxDynamicSharedMemorySize, 2 * BUF_SZ);
    cudaFuncSetAttribute(attn_mma,    cudaFuncAttributeMaxDynamicSharedMemorySize, AT_SMEM);

    decompose_x<<<(MROWS * DD / 4) / 256, 256>>>(x);
    decompose_wT<<<dim3(32, 32, 4), 256>>>(Wq, Wk, Wv, Wo);

    mma_gemm<0><<<dim3(8, 64, 3), 256, 2 * BUF_SZ>>>(bq, bk, bv, nullptr);

    attn_mma<<<dim3(32, 64), 128, AT_SMEM>>>();

    mma_gemm<1><<<dim3(8, 64, 1), 256, 2 * BUF_SZ>>>(bo, nullptr, nullptr, (float*)d_out);
}

// round 7
// speedup vs baseline: 14.2450x; 2.1967x over previous
#include <cuda_runtime.h>
#include <cuda_fp16.h>
#include <cstdint>

// Problem constants (fixed by setup_inputs)
#define TT    2048
#define DD    1024
#define HH    16
#define HDIM  64
#define BB    4
#define NBH   64        // B*H
#define MROWS 8192      // B*T

// ---------------- scratch (no cudaMalloc allowed) ----------------
__device__ __align__(16) __half g_xf[(size_t)MROWS * DD];          // x fp16
__device__ __align__(16) __half g_wTf[(size_t)4 * DD * DD];        // [z][n][k]
__device__ __align__(16) __half g_qf[(size_t)NBH * TT * HDIM];     // [bh][t][d]
__device__ __align__(16) __half g_kf[(size_t)NBH * TT * HDIM];
__device__ __align__(16) __half g_vTf[(size_t)NBH * HDIM * TT];    // [bh][d][t]
__device__ __align__(16) __half g_cf[(size_t)MROWS * DD];          // ctx fp16

// ---------------- PTX helpers ----------------
__device__ __forceinline__ void mma_f16(float* c, const unsigned* a, const unsigned* b) {
    asm volatile(
        "mma.sync.aligned.m16n8k16.row.col.f32.f16.f16.f32 "
        "{%0,%1,%2,%3}, {%4,%5,%6,%7}, {%8,%9}, {%0,%1,%2,%3};\n"
        : "+f"(c[0]), "+f"(c[1]), "+f"(c[2]), "+f"(c[3])
        : "r"(a[0]), "r"(a[1]), "r"(a[2]), "r"(a[3]), "r"(b[0]), "r"(b[1]));
}

__device__ __forceinline__ void ldsm_x4(unsigned* r, unsigned addr) {
    asm volatile("ldmatrix.sync.aligned.m8n8.x4.shared.b16 {%0,%1,%2,%3}, [%4];\n"
                 : "=r"(r[0]), "=r"(r[1]), "=r"(r[2]), "=r"(r[3]) : "r"(addr));
}

__device__ __forceinline__ void cp16(unsigned smem, const void* g) {
    asm volatile("cp.async.ca.shared.global [%0], [%1], 16;\n" :: "r"(smem), "l"(g));
}
#define CP_COMMIT()  asm volatile("cp.async.commit_group;\n" ::: "memory")
#define CP_WAIT_2()  asm volatile("cp.async.wait_group 2;\n" ::: "memory")
#define CP_WAIT_1()  asm volatile("cp.async.wait_group 1;\n" ::: "memory")
#define CP_WAIT_0()  asm volatile("cp.async.wait_group 0;\n" ::: "memory")

__device__ __forceinline__ float ex2(float x) {
    float y; asm("ex2.approx.ftz.f32 %0, %1;\n" : "=f"(y) : "f"(x)); return y;
}

__device__ __forceinline__ unsigned pack_h2(float a, float b) {
    __half2 h = __floats2half2_rn(a, b);
    return *(unsigned*)&h;
}

#define QSCALE (0.125f * 1.4426950408889634f)   // hd^-0.5 * log2(e)

// ---------------- fp16 conversion kernels ----------------
__global__ void __launch_bounds__(256) conv_x(const float* __restrict__ in) {
    int i = blockIdx.x * 256 + threadIdx.x;            // indexes float4
    float4 v = ((const float4*)in)[i];
    uint2 o;
    o.x = pack_h2(v.x, v.y);
    o.y = pack_h2(v.z, v.w);
    ((uint2*)g_xf)[i] = o;
}

// W [k][n] row-major  ->  WT fp16 [n][k]  (z: 0=q 1=k 2=v 3=o)
__global__ void __launch_bounds__(256) conv_wT(
    const float* __restrict__ Wq, const float* __restrict__ Wk,
    const float* __restrict__ Wv, const float* __restrict__ Wo)
{
    const int z = blockIdx.z;
    const float* W = (z == 0) ? Wq : (z == 1) ? Wk : (z == 2) ? Wv : Wo;
    __shared__ float tile[32][33];
    const int n0 = blockIdx.x * 32, k0 = blockIdx.y * 32;
    const int tx = threadIdx.x & 31, ty = threadIdx.x >> 5;
#pragma unroll
    for (int r = 0; r < 32; r += 8)
        tile[ty + r][tx] = W[(size_t)(k0 + ty + r) * DD + n0 + tx];
    __syncthreads();
#pragma unroll
    for (int r = 0; r < 32; r += 8) {
        size_t o = (size_t)z * DD * DD + (size_t)(n0 + ty + r) * DD + k0 + tx;
        g_wTf[o] = __float2half_rn(tile[tx][ty + r]);
    }
}

// ---------------------------------------------------------------------------
// fp16 tensor-core GEMM: C tile 128x128, BK=32 (two k16 sub-slabs), 256 threads
// (8 warps of 64x32), 3-stage cp.async pipeline. Rows of 16 halves at 48B pitch
// (32B data + 16B pad) -> conflict-free ldmatrix. Stage: A 12KB + B 12KB.
// ---------------------------------------------------------------------------
#define SLAB_SZ  6144            // 128 rows * 48B (one k16 sub-slab)
#define STG_SZ   24576           // A(2 slabs) + B(2 slabs)
#define GM_SMEM  (3 * STG_SZ)    // 73728

__device__ __forceinline__ void gemm_prefetch(
    unsigned sb, int stage, int k0,
    const __half* __restrict__ Af, const __half* __restrict__ Bf,
    int bm, int bn, int t)
{
    const unsigned base = sb + stage * STG_SZ;
#pragma unroll
    for (int r = 0; r < 2; r++) {                 // A: 512 x 16B
        int idx = t + 256 * r;
        int m = idx >> 2, q = idx & 3;
        int s = q >> 1, c = q & 1;
        cp16(base + s * SLAB_SZ + m * 48 + c * 16,
             Af + (size_t)(bm + m) * DD + k0 + s * 16 + c * 8);
    }
#pragma unroll
    for (int r = 0; r < 2; r++) {                 // B: 512 x 16B
        int idx = t + 256 * r;
        int n = idx >> 2, q = idx & 3;
        int s = q >> 1, c = q & 1;
        cp16(base + 12288u + s * SLAB_SZ + n * 48 + c * 16,
             Bf + (size_t)(bn + n) * DD + k0 + s * 16 + c * 8);
    }
}

// MODE 0: QKV (z = blockIdx.z; q scaled; head-scatter epilogue, fp16 out)
// MODE 1: out projection (fp32 out + bias)
template<int MODE>
__global__ void __launch_bounds__(256, 2) hgemm(
    const float* __restrict__ biasA, const float* __restrict__ biasB,
    const float* __restrict__ biasC, float* __restrict__ outp)
{
    extern __shared__ __align__(16) char dsm[];
    const unsigned sb = (unsigned)__cvta_generic_to_shared(dsm);

    const int z = (MODE == 0) ? blockIdx.z : 3;
    const __half* Af = (MODE == 0) ? g_xf : g_cf;
    const __half* Bf = g_wTf + (size_t)z * DD * DD;
    const float* bias = (MODE == 0) ? ((z == 0) ? biasA : (z == 1) ? biasB : biasC)
                                    : biasA;
    const float scale = (MODE == 0 && z == 0) ? QSCALE : 1.0f;

    const int t = threadIdx.x;
    const int bm = blockIdx.y << 7;
    const int bn = blockIdx.x << 7;
    const int wid = t >> 5, lane = t & 31;
    const int wm = (wid & 1) << 6;       // warp m offset
    const int wn = (wid >> 1) << 5;      // warp n offset

    float acc[4][4][4];
#pragma unroll
    for (int i = 0; i < 4; i++)
#pragma unroll
        for (int j = 0; j < 4; j++)
#pragma unroll
            for (int r = 0; r < 4; r++) acc[i][j][r] = 0.f;

    const unsigned a_row_off = (unsigned)((wm + (lane & 15)) * 48 + ((lane >> 4) << 4));
    const unsigned b_row_off = (unsigned)((wn + ((lane >> 4) << 3) + (lane & 7)) * 48 +
                                          (((lane >> 3) & 1) << 4));

    gemm_prefetch(sb, 0, 0,  Af, Bf, bm, bn, t); CP_COMMIT();
    gemm_prefetch(sb, 1, 32, Af, Bf, bm, bn, t); CP_COMMIT();

    const int NIT = DD / 32;   // 32 iterations of BK=32
    for (int it = 0; it < NIT; ++it) {
        if (it + 2 < NIT) {
            gemm_prefetch(sb, (it + 2) % 3, (it + 2) * 32, Af, Bf, bm, bn, t);
            CP_COMMIT();
            CP_WAIT_2();
        } else if (it == NIT - 2) {
            CP_WAIT_1();
        } else {
            CP_WAIT_0();
        }
        __syncthreads();

        const unsigned base = sb + (it % 3) * STG_SZ;
#pragma unroll
        for (int s = 0; s < 2; s++) {
            const unsigned bbase = base + 12288u + s * SLAB_SZ + b_row_off;
            unsigned bfr[8];
            ldsm_x4(bfr,     bbase);
            ldsm_x4(bfr + 4, bbase + 16 * 48);
            const unsigned abase = base + s * SLAB_SZ + a_row_off;
#pragma unroll
            for (int i = 0; i < 4; i++) {
                unsigned afr[4];
                ldsm_x4(afr, abase + i * 16 * 48);
#pragma unroll
                for (int j = 0; j < 4; j++)
                    mma_f16(acc[i][j], afr, bfr + 2 * j);
            }
        }
        __syncthreads();
    }

    // epilogue
    const int gg = lane >> 2, tg = lane & 3;
#pragma unroll
    for (int i = 0; i < 4; i++) {
#pragma unroll
        for (int j = 0; j < 4; j++) {
            const int row = bm + wm + 16 * i + gg;
            const int col = bn + wn + 8 * j + 2 * tg;
            float v00 = (acc[i][j][0] + bias[col])     * scale;
            float v01 = (acc[i][j][1] + bias[col + 1]) * scale;
            float v10 = (acc[i][j][2] + bias[col])     * scale;
            float v11 = (acc[i][j][3] + bias[col + 1]) * scale;
            if (MODE == 0) {
                const int head = col >> 6, d = col & 63;
                const int b0_ = row >> 11, t0_ = row & 2047;
                const int t1_ = (row + 8) & 2047;      // row+8 stays in same b
                const int bh_ = b0_ * 16 + head;
                if (z == 2) {
                    // vT: [bh][d][t]
                    size_t r0 = ((size_t)bh_ * 64 + d) * 2048;
                    size_t r1 = ((size_t)bh_ * 64 + d + 1) * 2048;
                    g_vTf[r0 + t0_] = __float2half_rn(v00);
                    g_vTf[r1 + t0_] = __float2half_rn(v01);
                    g_vTf[r0 + t1_] = __float2half_rn(v10);
                    g_vTf[r1 + t1_] = __float2half_rn(v11);
                } else {
                    __half* dst = (z == 0) ? g_qf : g_kf;
                    size_t o0 = ((size_t)bh_ * 2048 + t0_) * 64 + d;
                    size_t o1 = ((size_t)bh_ * 2048 + t1_) * 64 + d;
                    *(unsigned*)(dst + o0) = pack_h2(v00, v01);
                    *(unsigned*)(dst + o1) = pack_h2(v10, v11);
                }
            } else {
                outp[(size_t)row * DD + col]           = v00;
                outp[(size_t)row * DD + col + 1]       = v01;
                outp[(size_t)(row + 8) * DD + col]     = v10;
                outp[(size_t)(row + 8) * DD + col + 1] = v11;
            }
        }
    }
}

// ---------------------------------------------------------------------------
// fp16 tensor-core BD3LM attention. Block = (bh, 64-row q-tile), 128 threads
// (4 warps, each m16 x n64). K tiles [kv][64], V^T tiles [d][kv], 144B pitch.
// Scores in log2 units (QSCALE folded into q), ex2 softmax.
// ---------------------------------------------------------------------------
#define AT_PITCH  144
#define AT_ARR    (64 * AT_PITCH)     // 9216
#define AT_BUF    (2 * AT_ARR)        // 18432 (K, V)
#define AT_SMEM   (2 * AT_BUF)        // 36864

__global__ void __launch_bounds__(128) attn_mma()
{
    extern __shared__ __align__(16) char dsm[];
    const unsigned sb = (unsigned)__cvta_generic_to_shared(dsm);

    const int bi = blockIdx.x;
    // heavy-first ordering: xt qt has qt+2 tiles, x0 qt has qt-15
    const int qt = (bi & 1) ? (31 - (bi >> 1)) : (15 - (bi >> 1));
    const int bh = blockIdx.y;
    const int qt0 = qt << 6;
    const int tid = threadIdx.x;
    const int lane = tid & 31, warp = tid >> 5;
    const int wm = warp << 4;
    const int g = lane >> 2, tq = lane & 3;

    // ---- stage Q into smem buffer 0 (consumed before the loop) ----
#pragma unroll
    for (int i = 0; i < 4; i++) {
        int idx = tid + (i << 7);
        int r = idx >> 3, c = idx & 7;
        cp16(sb + r * AT_PITCH + c * 16,
             g_qf + ((size_t)bh * 2048 + qt0 + r) * 64 + c * 8);
    }
    CP_COMMIT();
    CP_WAIT_0();
    __syncthreads();

    unsigned qf[4][4];
    const unsigned a_off = (unsigned)((wm + (lane & 15)) * AT_PITCH + ((lane >> 4) << 4));
#pragma unroll
    for (int c = 0; c < 4; c++)
        ldsm_x4(qf[c], sb + a_off + c * 32);
    __syncthreads();

    float o[8][4];
#pragma unroll
    for (int j = 0; j < 8; j++)
#pragma unroll
        for (int k = 0; k < 4; k++) o[j][k] = 0.f;
    float m0 = -1e30f, m1 = -1e30f, l0 = 0.f, l1 = 0.f;

    const bool is_x0 = (qt >= 16);
    const int nfull  = is_x0 ? (qt - 16) : qt;
    const int ntiles = nfull + (is_x0 ? 1 : 2);

    auto tile_of = [&](int it, int& s, int& mode) {
        if (it < nfull)        { s = 1024 + (it << 6); mode = 0; }
        else if (is_x0)        { s = qt0;              mode = 1; }
        else if (it == nfull)  { s = 1024 + qt0;       mode = 2; }
        else                   { s = qt0;              mode = 3; }
    };

    auto prefetch = [&](int s, int buf) {
        unsigned dstb = sb + buf * AT_BUF;
#pragma unroll
        for (int i = 0; i < 8; i++) {
            int idx = tid + (i << 7);
            int arr = idx >> 9, rem = idx & 511;
            int r = rem >> 3, c = rem & 7;
            const __half* src = (arr == 0)
                ? g_kf  + ((size_t)bh * 2048 + s + r) * 64 + c * 8
                : g_vTf + ((size_t)bh * 64 + r) * 2048 + s + c * 8;
            cp16(dstb + arr * AT_ARR + r * AT_PITCH + c * 16, src);
        }
    };

    {
        int s0, md0; tile_of(0, s0, md0);
        prefetch(s0, 0);
        CP_COMMIT();
    }

    const unsigned b_off = (unsigned)((((lane >> 4) << 3) + (lane & 7)) * AT_PITCH +
                                      (((lane >> 3) & 1) << 4));

    for (int it = 0; it < ntiles; ++it) {
        int s_, mode; tile_of(it, s_, mode);
        if (it + 1 < ntiles) {
            int sn, mn; tile_of(it + 1, sn, mn);
            prefetch(sn, (it + 1) & 1);
            CP_COMMIT();
            CP_WAIT_1();
        } else {
            CP_WAIT_0();
        }
        __syncthreads();

        const unsigned base = sb + (it & 1) * AT_BUF;

        // ---- S = Q K^T ----
        float sc[8][4];
#pragma unroll
        for (int j = 0; j < 8; j++)
#pragma unroll
            for (int k = 0; k < 4; k++) sc[j][k] = 0.f;

#pragma unroll
        for (int c = 0; c < 4; c++) {
#pragma unroll
            for (int p = 0; p < 4; p++) {
                unsigned kb[4];
                ldsm_x4(kb, base + (p << 4) * AT_PITCH + b_off + c * 32);
                mma_f16(sc[2 * p],     qf[c], kb);
                mma_f16(sc[2 * p + 1], qf[c], kb + 2);
            }
        }

        // ---- mask (boundary tiles only): block index = idx>>2 ----
        if (mode) {
#pragma unroll
            for (int j = 0; j < 8; j++)
#pragma unroll
                for (int k = 0; k < 4; k++) {
                    int r = wm + g + ((k >> 1) << 3);
                    int c = (j << 3) + (tq << 1) + (k & 1);
                    int r2 = r >> 2, c2 = c >> 2;
                    bool ok = (mode == 1) ? (c2 <= r2) :
                              (mode == 2) ? (c2 <  r2) : (c2 == r2);
                    if (!ok) sc[j][k] = -1e30f;
                }
        }

        // ---- online softmax (rows g / g+8; quad shfl over tq) ----
        float t0 = -1e30f, t1 = -1e30f;
#pragma unroll
        for (int j = 0; j < 8; j++) {
            t0 = fmaxf(t0, fmaxf(sc[j][0], sc[j][1]));
            t1 = fmaxf(t1, fmaxf(sc[j][2], sc[j][3]));
        }
        t0 = fmaxf(t0, __shfl_xor_sync(0xffffffffu, t0, 1));
        t0 = fmaxf(t0, __shfl_xor_sync(0xffffffffu, t0, 2));
        t1 = fmaxf(t1, __shfl_xor_sync(0xffffffffu, t1, 1));
        t1 = fmaxf(t1, __shfl_xor_sync(0xffffffffu, t1, 2));
        const float mn0 = fmaxf(m0, t0), mn1 = fmaxf(m1, t1);
        const float r0 = ex2(m0 - mn0), r1 = ex2(m1 - mn1);
        float ls0 = 0.f, ls1 = 0.f;
#pragma unroll
        for (int j = 0; j < 8; j++) {
            sc[j][0] = ex2(sc[j][0] - mn0);
            sc[j][1] = ex2(sc[j][1] - mn0);
            sc[j][2] = ex2(sc[j][2] - mn1);
            sc[j][3] = ex2(sc[j][3] - mn1);
            ls0 += sc[j][0] + sc[j][1];
            ls1 += sc[j][2] + sc[j][3];
        }
        ls0 += __shfl_xor_sync(0xffffffffu, ls0, 1);
        ls0 += __shfl_xor_sync(0xffffffffu, ls0, 2);
        ls1 += __shfl_xor_sync(0xffffffffu, ls1, 1);
        ls1 += __shfl_xor_sync(0xffffffffu, ls1, 2);
        l0 = l0 * r0 + ls0;  m0 = mn0;
        l1 = l1 * r1 + ls1;  m1 = mn1;
#pragma unroll
        for (int j = 0; j < 8; j++) {
            o[j][0] *= r0; o[j][1] *= r0;
            o[j][2] *= r1; o[j][3] *= r1;
        }

        // ---- O += P V (P repacked accumulator -> A fragment, fp16) ----
#pragma unroll
        for (int c = 0; c < 4; c++) {
            unsigned pf[4];
            pf[0] = pack_h2(sc[2 * c][0],     sc[2 * c][1]);
            pf[1] = pack_h2(sc[2 * c][2],     sc[2 * c][3]);
            pf[2] = pack_h2(sc[2 * c + 1][0], sc[2 * c + 1][1]);
            pf[3] = pack_h2(sc[2 * c + 1][2], sc[2 * c + 1][3]);
#pragma unroll
            for (int p = 0; p < 4; p++) {
                unsigned vb[4];
                ldsm_x4(vb, base + AT_ARR + (p << 4) * AT_PITCH + b_off + c * 32);
                mma_f16(o[2 * p],     pf, vb);
                mma_f16(o[2 * p + 1], pf, vb + 2);
            }
        }
        __syncthreads();
    }

    // ---- epilogue: normalize, store ctx [B*T][D] fp16 ----
    const float inv0 = 1.f / l0, inv1 = 1.f / l1;
    const int b_ = bh >> 4, h_ = bh & 15;
    const int row0 = qt0 + wm + g;
    __half* c0 = g_cf + ((size_t)b_ * 2048 + row0) * 1024 + h_ * 64 + (tq << 1);
#pragma unroll
    for (int j = 0; j < 8; j++) {
        *(unsigned*)(c0 + (j << 3)) = pack_h2(o[j][0] * inv0, o[j][1] * inv0);
        *(unsigned*)(c0 + 8 * 1024 + (j << 3)) = pack_h2(o[j][2] * inv1, o[j][3] * inv1);
    }
}

// ---------------------------------------------------------------------------

extern "C" void kernel_launch(void* const* d_in, const int* in_sizes, int n_in,
                              void* d_out, int out_size)
{
    const float* x  = (const float*)d_in[0];
    const float* Wq = (const float*)d_in[1];
    const float* bq = (const float*)d_in[2];
    const float* Wk = (const float*)d_in[3];
    const float* bk = (const float*)d_in[4];
    const float* Wv = (const float*)d_in[5];
    const float* bv = (const float*)d_in[6];
    const float* Wo = (const float*)d_in[7];
    const float* bo = (const float*)d_in[8];

    cudaFuncSetAttribute(hgemm<0>, cudaFuncAttributeMaxDynamicSharedMemorySize, GM_SMEM);
    cudaFuncSetAttribute(hgemm<1>, cudaFuncAttributeMaxDynamicSharedMemorySize, GM_SMEM);

    conv_x<<<(MROWS * DD / 4) / 256, 256>>>(x);
    conv_wT<<<dim3(32, 32, 4), 256>>>(Wq, Wk, Wv, Wo);

    hgemm<0><<<dim3(8, 64, 3), 256, GM_SMEM>>>(bq, bk, bv, nullptr);

    attn_mma<<<dim3(32, 64), 128, AT_SMEM>>>();

    hgemm<1><<<dim3(8, 64), 256, GM_SMEM>>>(bo, nullptr, nullptr, (float*)d_out);
}

// round 8
// speedup vs baseline: 14.8924x; 1.0455x over previous
#include <cuda_runtime.h>
#include <cuda_fp16.h>
#include <cstdint>

// Problem constants (fixed by setup_inputs)
#define TT    2048
#define DD    1024
#define HH    16
#define HDIM  64
#define BB    4
#define NBH   64        // B*H
#define MROWS 8192      // B*T

// ---------------- scratch (no cudaMalloc allowed) ----------------
__device__ __align__(16) __half g_xf[(size_t)MROWS * DD];          // x fp16
__device__ __align__(16) __half g_wTf[(size_t)4 * DD * DD];        // [z][n][k]
__device__ __align__(16) __half g_qf[(size_t)NBH * TT * HDIM];     // [bh][t][d]
__device__ __align__(16) __half g_kf[(size_t)NBH * TT * HDIM];
__device__ __align__(16) __half g_vTf[(size_t)NBH * HDIM * TT];    // [bh][d][t]
__device__ __align__(16) __half g_cf[(size_t)MROWS * DD];          // ctx fp16

// ---------------- PTX helpers ----------------
__device__ __forceinline__ void mma_f16(float* c, const unsigned* a, const unsigned* b) {
    asm volatile(
        "mma.sync.aligned.m16n8k16.row.col.f32.f16.f16.f32 "
        "{%0,%1,%2,%3}, {%4,%5,%6,%7}, {%8,%9}, {%0,%1,%2,%3};\n"
        : "+f"(c[0]), "+f"(c[1]), "+f"(c[2]), "+f"(c[3])
        : "r"(a[0]), "r"(a[1]), "r"(a[2]), "r"(a[3]), "r"(b[0]), "r"(b[1]));
}

__device__ __forceinline__ void ldsm_x4(unsigned* r, unsigned addr) {
    asm volatile("ldmatrix.sync.aligned.m8n8.x4.shared.b16 {%0,%1,%2,%3}, [%4];\n"
                 : "=r"(r[0]), "=r"(r[1]), "=r"(r[2]), "=r"(r[3]) : "r"(addr));
}

__device__ __forceinline__ void cp16(unsigned smem, const void* g) {
    asm volatile("cp.async.ca.shared.global [%0], [%1], 16;\n" :: "r"(smem), "l"(g));
}
#define CP_COMMIT()  asm volatile("cp.async.commit_group;\n" ::: "memory")
#define CP_WAIT_2()  asm volatile("cp.async.wait_group 2;\n" ::: "memory")
#define CP_WAIT_1()  asm volatile("cp.async.wait_group 1;\n" ::: "memory")
#define CP_WAIT_0()  asm volatile("cp.async.wait_group 0;\n" ::: "memory")

__device__ __forceinline__ float ex2(float x) {
    float y; asm("ex2.approx.ftz.f32 %0, %1;\n" : "=f"(y) : "f"(x)); return y;
}

__device__ __forceinline__ unsigned pack_h2(float a, float b) {
    __half2 h = __floats2half2_rn(a, b);
    return *(unsigned*)&h;
}

#define QSCALE (0.125f * 1.4426950408889634f)   // hd^-0.5 * log2(e)

// ---------------- fp16 conversion kernels ----------------
__global__ void __launch_bounds__(256) conv_x(const float* __restrict__ in) {
    int i = blockIdx.x * 256 + threadIdx.x;            // indexes float4
    float4 v = ((const float4*)in)[i];
    uint2 o;
    o.x = pack_h2(v.x, v.y);
    o.y = pack_h2(v.z, v.w);
    ((uint2*)g_xf)[i] = o;
}

// W [k][n] row-major  ->  WT fp16 [n][k]  (z: 0=q 1=k 2=v 3=o)
__global__ void __launch_bounds__(256) conv_wT(
    const float* __restrict__ Wq, const float* __restrict__ Wk,
    const float* __restrict__ Wv, const float* __restrict__ Wo)
{
    const int z = blockIdx.z;
    const float* W = (z == 0) ? Wq : (z == 1) ? Wk : (z == 2) ? Wv : Wo;
    __shared__ float tile[32][33];
    const int n0 = blockIdx.x * 32, k0 = blockIdx.y * 32;
    const int tx = threadIdx.x & 31, ty = threadIdx.x >> 5;
#pragma unroll
    for (int r = 0; r < 32; r += 8)
        tile[ty + r][tx] = W[(size_t)(k0 + ty + r) * DD + n0 + tx];
    __syncthreads();
#pragma unroll
    for (int r = 0; r < 32; r += 8) {
        size_t o = (size_t)z * DD * DD + (size_t)(n0 + ty + r) * DD + k0 + tx;
        g_wTf[o] = __float2half_rn(tile[tx][ty + r]);
    }
}

// ---------------------------------------------------------------------------
// fp16 tensor-core GEMM: C tile 128x128, BK=32 (two k16 sub-slabs), 256 threads
// (8 warps of 64x32), 4-stage cp.async pipeline, ONE barrier per iteration.
// Rows of 16 halves at 48B pitch -> conflict-free ldmatrix. Stage = 24KB.
// ---------------------------------------------------------------------------
#define SLAB_SZ  6144            // 128 rows * 48B (one k16 sub-slab)
#define STG_SZ   24576           // A(2 slabs) + B(2 slabs)
#define GM_SMEM  (4 * STG_SZ)    // 98304

__device__ __forceinline__ void gemm_prefetch(
    unsigned sb, int stage, int k0,
    const __half* __restrict__ Af, const __half* __restrict__ Bf,
    int bm, int bn, int t)
{
    const unsigned base = sb + stage * STG_SZ;
#pragma unroll
    for (int r = 0; r < 2; r++) {                 // A: 512 x 16B
        int idx = t + 256 * r;
        int m = idx >> 2, q = idx & 3;
        int s = q >> 1, c = q & 1;
        cp16(base + s * SLAB_SZ + m * 48 + c * 16,
             Af + (size_t)(bm + m) * DD + k0 + s * 16 + c * 8);
    }
#pragma unroll
    for (int r = 0; r < 2; r++) {                 // B: 512 x 16B
        int idx = t + 256 * r;
        int n = idx >> 2, q = idx & 3;
        int s = q >> 1, c = q & 1;
        cp16(base + 12288u + s * SLAB_SZ + n * 48 + c * 16,
             Bf + (size_t)(bn + n) * DD + k0 + s * 16 + c * 8);
    }
}

// MODE 0: QKV (z = blockIdx.z; q scaled; head-scatter epilogue, fp16 out)
// MODE 1: out projection (fp32 out + bias)
template<int MODE>
__global__ void __launch_bounds__(256, 2) hgemm(
    const float* __restrict__ biasA, const float* __restrict__ biasB,
    const float* __restrict__ biasC, float* __restrict__ outp)
{
    extern __shared__ __align__(16) char dsm[];
    const unsigned sb = (unsigned)__cvta_generic_to_shared(dsm);

    const int z = (MODE == 0) ? blockIdx.z : 3;
    const __half* Af = (MODE == 0) ? g_xf : g_cf;
    const __half* Bf = g_wTf + (size_t)z * DD * DD;
    const float* bias = (MODE == 0) ? ((z == 0) ? biasA : (z == 1) ? biasB : biasC)
                                    : biasA;
    const float scale = (MODE == 0 && z == 0) ? QSCALE : 1.0f;

    const int t = threadIdx.x;
    const int bm = blockIdx.y << 7;
    const int bn = blockIdx.x << 7;
    const int wid = t >> 5, lane = t & 31;
    const int wm = (wid & 1) << 6;       // warp m offset
    const int wn = (wid >> 1) << 5;      // warp n offset

    float acc[4][4][4];
#pragma unroll
    for (int i = 0; i < 4; i++)
#pragma unroll
        for (int j = 0; j < 4; j++)
#pragma unroll
            for (int r = 0; r < 4; r++) acc[i][j][r] = 0.f;

    const unsigned a_row_off = (unsigned)((wm + (lane & 15)) * 48 + ((lane >> 4) << 4));
    const unsigned b_row_off = (unsigned)((wn + ((lane >> 4) << 3) + (lane & 7)) * 48 +
                                          (((lane >> 3) & 1) << 4));

    gemm_prefetch(sb, 0, 0,  Af, Bf, bm, bn, t); CP_COMMIT();
    gemm_prefetch(sb, 1, 32, Af, Bf, bm, bn, t); CP_COMMIT();
    gemm_prefetch(sb, 2, 64, Af, Bf, bm, bn, t); CP_COMMIT();

    const int NIT = DD / 32;   // 32 iterations of BK=32
    for (int it = 0; it < NIT; ++it) {
        if (it < NIT - 2)      { CP_WAIT_2(); }
        else if (it == NIT - 2){ CP_WAIT_1(); }
        else                   { CP_WAIT_0(); }
        __syncthreads();   // stage 'it' globally ready; all warps done reading it-1

        const unsigned base = sb + (it & 3) * STG_SZ;
#pragma unroll
        for (int s = 0; s < 2; s++) {
            const unsigned bbase = base + 12288u + s * SLAB_SZ + b_row_off;
            unsigned bfr[8];
            ldsm_x4(bfr,     bbase);
            ldsm_x4(bfr + 4, bbase + 16 * 48);
            const unsigned abase = base + s * SLAB_SZ + a_row_off;
#pragma unroll
            for (int i = 0; i < 4; i++) {
                unsigned afr[4];
                ldsm_x4(afr, abase + i * 16 * 48);
#pragma unroll
                for (int j = 0; j < 4; j++)
                    mma_f16(acc[i][j], afr, bfr + 2 * j);
            }
        }

        if (it + 3 < NIT) {    // refill buffer consumed at it-1
            gemm_prefetch(sb, (it + 3) & 3, (it + 3) * 32, Af, Bf, bm, bn, t);
            CP_COMMIT();
        }
    }

    // epilogue
    const int gg = lane >> 2, tg = lane & 3;
#pragma unroll
    for (int i = 0; i < 4; i++) {
#pragma unroll
        for (int j = 0; j < 4; j++) {
            const int row = bm + wm + 16 * i + gg;
            const int col = bn + wn + 8 * j + 2 * tg;
            float v00 = (acc[i][j][0] + bias[col])     * scale;
            float v01 = (acc[i][j][1] + bias[col + 1]) * scale;
            float v10 = (acc[i][j][2] + bias[col])     * scale;
            float v11 = (acc[i][j][3] + bias[col + 1]) * scale;
            if (MODE == 0) {
                const int head = col >> 6, d = col & 63;
                const int b0_ = row >> 11, t0_ = row & 2047;
                const int t1_ = (row + 8) & 2047;      // row+8 stays in same b
                const int bh_ = b0_ * 16 + head;
                if (z == 2) {
                    // vT: [bh][d][t]
                    size_t r0 = ((size_t)bh_ * 64 + d) * 2048;
                    size_t r1 = ((size_t)bh_ * 64 + d + 1) * 2048;
                    g_vTf[r0 + t0_] = __float2half_rn(v00);
                    g_vTf[r1 + t0_] = __float2half_rn(v01);
                    g_vTf[r0 + t1_] = __float2half_rn(v10);
                    g_vTf[r1 + t1_] = __float2half_rn(v11);
                } else {
                    __half* dst = (z == 0) ? g_qf : g_kf;
                    size_t o0 = ((size_t)bh_ * 2048 + t0_) * 64 + d;
                    size_t o1 = ((size_t)bh_ * 2048 + t1_) * 64 + d;
                    *(unsigned*)(dst + o0) = pack_h2(v00, v01);
                    *(unsigned*)(dst + o1) = pack_h2(v10, v11);
                }
            } else {
                outp[(size_t)row * DD + col]           = v00;
                outp[(size_t)row * DD + col + 1]       = v01;
                outp[(size_t)(row + 8) * DD + col]     = v10;
                outp[(size_t)(row + 8) * DD + col + 1] = v11;
            }
        }
    }
}

// ---------------------------------------------------------------------------
// fp16 tensor-core BD3LM attention. Block = (bh, 64-row q-tile), 128 threads
// (4 warps, each m16 x n64). K tiles [kv][64], V^T tiles [d][kv], 144B pitch.
// 3 KV buffers, ONE barrier per tile, 2-tile prefetch lookahead.
// ---------------------------------------------------------------------------
#define AT_PITCH  144
#define AT_ARR    (64 * AT_PITCH)     // 9216
#define AT_BUF    (2 * AT_ARR)        // 18432 (K, V)
#define AT_SMEM   (3 * AT_BUF)        // 55296

__global__ void __launch_bounds__(128, 4) attn_mma()
{
    extern __shared__ __align__(16) char dsm[];
    const unsigned sb = (unsigned)__cvta_generic_to_shared(dsm);

    const int bi = blockIdx.x;
    // heavy-first ordering: xt qt has qt+2 tiles, x0 qt has qt-15
    const int qt = (bi & 1) ? (31 - (bi >> 1)) : (15 - (bi >> 1));
    const int bh = blockIdx.y;
    const int qt0 = qt << 6;
    const int tid = threadIdx.x;
    const int lane = tid & 31, warp = tid >> 5;
    const int wm = warp << 4;
    const int g = lane >> 2, tq = lane & 3;

    // ---- stage Q into buffer 0 region (consumed into regs before prefetch) ----
#pragma unroll
    for (int i = 0; i < 4; i++) {
        int idx = tid + (i << 7);
        int r = idx >> 3, c = idx & 7;
        cp16(sb + r * AT_PITCH + c * 16,
             g_qf + ((size_t)bh * 2048 + qt0 + r) * 64 + c * 8);
    }
    CP_COMMIT();
    CP_WAIT_0();
    __syncthreads();

    unsigned qf[4][4];
    const unsigned a_off = (unsigned)((wm + (lane & 15)) * AT_PITCH + ((lane >> 4) << 4));
#pragma unroll
    for (int c = 0; c < 4; c++)
        ldsm_x4(qf[c], sb + a_off + c * 32);
    __syncthreads();   // Q fully read before prefetch overwrites buffer 0

    float o[8][4];
#pragma unroll
    for (int j = 0; j < 8; j++)
#pragma unroll
        for (int k = 0; k < 4; k++) o[j][k] = 0.f;
    float m0 = -1e30f, m1 = -1e30f, l0 = 0.f, l1 = 0.f;

    const bool is_x0 = (qt >= 16);
    const int nfull  = is_x0 ? (qt - 16) : qt;
    const int ntiles = nfull + (is_x0 ? 1 : 2);

    auto tile_of = [&](int it, int& s, int& mode) {
        if (it < nfull)        { s = 1024 + (it << 6); mode = 0; }
        else if (is_x0)        { s = qt0;              mode = 1; }
        else if (it == nfull)  { s = 1024 + qt0;       mode = 2; }
        else                   { s = qt0;              mode = 3; }
    };

    auto prefetch = [&](int s, int buf) {
        unsigned dstb = sb + buf * AT_BUF;
#pragma unroll
        for (int i = 0; i < 8; i++) {
            int idx = tid + (i << 7);
            int arr = idx >> 9, rem = idx & 511;
            int r = rem >> 3, c = rem & 7;
            const __half* src = (arr == 0)
                ? g_kf  + ((size_t)bh * 2048 + s + r) * 64 + c * 8
                : g_vTf + ((size_t)bh * 64 + r) * 2048 + s + c * 8;
            cp16(dstb + arr * AT_ARR + r * AT_PITCH + c * 16, src);
        }
    };

    {
        int s0, md; tile_of(0, s0, md);
        prefetch(s0, 0);
        CP_COMMIT();
        if (ntiles > 1) { int s1; tile_of(1, s1, md); prefetch(s1, 1); }
        CP_COMMIT();    // commit even if empty: keeps group counting uniform
    }

    const unsigned b_off = (unsigned)((((lane >> 4) << 3) + (lane & 7)) * AT_PITCH +
                                      (((lane >> 3) & 1) << 4));

    for (int it = 0; it < ntiles; ++it) {
        int s_, mode; tile_of(it, s_, mode);
        if (it < ntiles - 1) { CP_WAIT_1(); } else { CP_WAIT_0(); }
        __syncthreads();   // tile 'it' ready; all warps done reading it-1

        const unsigned base = sb + (it % 3) * AT_BUF;

        // ---- S = Q K^T ----
        float sc[8][4];
#pragma unroll
        for (int j = 0; j < 8; j++)
#pragma unroll
            for (int k = 0; k < 4; k++) sc[j][k] = 0.f;

#pragma unroll
        for (int c = 0; c < 4; c++) {
#pragma unroll
            for (int p = 0; p < 4; p++) {
                unsigned kb[4];
                ldsm_x4(kb, base + (p << 4) * AT_PITCH + b_off + c * 32);
                mma_f16(sc[2 * p],     qf[c], kb);
                mma_f16(sc[2 * p + 1], qf[c], kb + 2);
            }
        }

        // ---- mask (boundary tiles only): block index = idx>>2 ----
        if (mode) {
#pragma unroll
            for (int j = 0; j < 8; j++)
#pragma unroll
                for (int k = 0; k < 4; k++) {
                    int r = wm + g + ((k >> 1) << 3);
                    int c = (j << 3) + (tq << 1) + (k & 1);
                    int r2 = r >> 2, c2 = c >> 2;
                    bool ok = (mode == 1) ? (c2 <= r2) :
                              (mode == 2) ? (c2 <  r2) : (c2 == r2);
                    if (!ok) sc[j][k] = -1e30f;
                }
        }

        // ---- online softmax (rows g / g+8; quad shfl over tq) ----
        float t0 = -1e30f, t1 = -1e30f;
#pragma unroll
        for (int j = 0; j < 8; j++) {
            t0 = fmaxf(t0, fmaxf(sc[j][0], sc[j][1]));
            t1 = fmaxf(t1, fmaxf(sc[j][2], sc[j][3]));
        }
        t0 = fmaxf(t0, __shfl_xor_sync(0xffffffffu, t0, 1));
        t0 = fmaxf(t0, __shfl_xor_sync(0xffffffffu, t0, 2));
        t1 = fmaxf(t1, __shfl_xor_sync(0xffffffffu, t1, 1));
        t1 = fmaxf(t1, __shfl_xor_sync(0xffffffffu, t1, 2));
        const float mn0 = fmaxf(m0, t0), mn1 = fmaxf(m1, t1);
        const float r0 = ex2(m0 - mn0), r1 = ex2(m1 - mn1);
        float ls0 = 0.f, ls1 = 0.f;
#pragma unroll
        for (int j = 0; j < 8; j++) {
            sc[j][0] = ex2(sc[j][0] - mn0);
            sc[j][1] = ex2(sc[j][1] - mn0);
            sc[j][2] = ex2(sc[j][2] - mn1);
            sc[j][3] = ex2(sc[j][3] - mn1);
            ls0 += sc[j][0] + sc[j][1];
            ls1 += sc[j][2] + sc[j][3];
        }
        ls0 += __shfl_xor_sync(0xffffffffu, ls0, 1);
        ls0 += __shfl_xor_sync(0xffffffffu, ls0, 2);
        ls1 += __shfl_xor_sync(0xffffffffu, ls1, 1);
        ls1 += __shfl_xor_sync(0xffffffffu, ls1, 2);
        l0 = l0 * r0 + ls0;  m0 = mn0;
        l1 = l1 * r1 + ls1;  m1 = mn1;
#pragma unroll
        for (int j = 0; j < 8; j++) {
            o[j][0] *= r0; o[j][1] *= r0;
            o[j][2] *= r1; o[j][3] *= r1;
        }

        // ---- O += P V (P repacked accumulator -> A fragment, fp16) ----
#pragma unroll
        for (int c = 0; c < 4; c++) {
            unsigned pf[4];
            pf[0] = pack_h2(sc[2 * c][0],     sc[2 * c][1]);
            pf[1] = pack_h2(sc[2 * c][2],     sc[2 * c][3]);
            pf[2] = pack_h2(sc[2 * c + 1][0], sc[2 * c + 1][1]);
            pf[3] = pack_h2(sc[2 * c + 1][2], sc[2 * c + 1][3]);
#pragma unroll
            for (int p = 0; p < 4; p++) {
                unsigned vb[4];
                ldsm_x4(vb, base + AT_ARR + (p << 4) * AT_PITCH + b_off + c * 32);
                mma_f16(o[2 * p],     pf, vb);
                mma_f16(o[2 * p + 1], pf, vb + 2);
            }
        }

        if (it + 2 < ntiles) {   // refill buffer consumed at it-1
            int sn, mn; tile_of(it + 2, sn, mn);
            prefetch(sn, (it + 2) % 3);
            CP_COMMIT();
        }
    }

    // ---- epilogue: normalize, store ctx [B*T][D] fp16 ----
    const float inv0 = 1.f / l0, inv1 = 1.f / l1;
    const int b_ = bh >> 4, h_ = bh & 15;
    const int row0 = qt0 + wm + g;
    __half* c0 = g_cf + ((size_t)b_ * 2048 + row0) * 1024 + h_ * 64 + (tq << 1);
#pragma unroll
    for (int j = 0; j < 8; j++) {
        *(unsigned*)(c0 + (j << 3)) = pack_h2(o[j][0] * inv0, o[j][1] * inv0);
        *(unsigned*)(c0 + 8 * 1024 + (j << 3)) = pack_h2(o[j][2] * inv1, o[j][3] * inv1);
    }
}

// ---------------------------------------------------------------------------

extern "C" void kernel_launch(void* const* d_in, const int* in_sizes, int n_in,
                              void* d_out, int out_size)
{
    const float* x  = (const float*)d_in[0];
    const float* Wq = (const float*)d_in[1];
    const float* bq = (const float*)d_in[2];
    const float* Wk = (const float*)d_in[3];
    const float* bk = (const float*)d_in[4];
    const float* Wv = (const float*)d_in[5];
    const float* bv = (const float*)d_in[6];
    const float* Wo = (const float*)d_in[7];
    const float* bo = (const float*)d_in[8];

    cudaFuncSetAttribute(hgemm<0>, cudaFuncAttributeMaxDynamicSharedMemorySize, GM_SMEM);
    cudaFuncSetAttribute(hgemm<1>, cudaFuncAttributeMaxDynamicSharedMemorySize, GM_SMEM);
    cudaFuncSetAttribute(attn_mma, cudaFuncAttributeMaxDynamicSharedMemorySize, AT_SMEM);

    conv_x<<<(MROWS * DD / 4) / 256, 256>>>(x);
    conv_wT<<<dim3(32, 32, 4), 256>>>(Wq, Wk, Wv, Wo);

    hgemm<0><<<dim3(8, 64, 3), 256, GM_SMEM>>>(bq, bk, bv, nullptr);

    attn_mma<<<dim3(32, 64), 128, AT_SMEM>>>();

    hgemm<1><<<dim3(8, 64), 256, GM_SMEM>>>(bo, nullptr, nullptr, (float*)d_out);
}

// round 12
// speedup vs baseline: 18.1997x; 1.2221x over previous
#include <cuda_runtime.h>
#include <cuda_fp16.h>
#include <cstdint>

// Problem constants (fixed by setup_inputs)
#define TT    2048
#define DD    1024
#define HH    16
#define HDIM  64
#define BB    4
#define NBH   64        // B*H
#define MROWS 8192      // B*T

// ---------------- scratch (no cudaMalloc allowed) ----------------
__device__ __align__(16) __half g_xf[(size_t)MROWS * DD];          // x fp16
__device__ uint4 g_wF[(size_t)4 * 64 * 64 * 32];                   // W fragment blocks [z][nb][ks][lane]
__device__ __align__(16) __half g_qf[(size_t)NBH * TT * HDIM];     // [bh][t][d]
__device__ __align__(16) __half g_kf[(size_t)NBH * TT * HDIM];
__device__ __align__(16) __half g_vTf[(size_t)NBH * HDIM * TT];    // [bh][d][t]
__device__ __align__(16) __half g_cf[(size_t)MROWS * DD];          // ctx fp16

// ---------------- PTX helpers ----------------
__device__ __forceinline__ void mma_f16(float* c, const unsigned* a, const unsigned* b) {
    asm volatile(
        "mma.sync.aligned.m16n8k16.row.col.f32.f16.f16.f32 "
        "{%0,%1,%2,%3}, {%4,%5,%6,%7}, {%8,%9}, {%0,%1,%2,%3};\n"
        : "+f"(c[0]), "+f"(c[1]), "+f"(c[2]), "+f"(c[3])
        : "r"(a[0]), "r"(a[1]), "r"(a[2]), "r"(a[3]), "r"(b[0]), "r"(b[1]));
}

__device__ __forceinline__ void ldsm_x4(unsigned* r, unsigned addr) {
    asm volatile("ldmatrix.sync.aligned.m8n8.x4.shared.b16 {%0,%1,%2,%3}, [%4];\n"
                 : "=r"(r[0]), "=r"(r[1]), "=r"(r[2]), "=r"(r[3]) : "r"(addr));
}

__device__ __forceinline__ void cp16(unsigned smem, const void* g) {
    asm volatile("cp.async.ca.shared.global [%0], [%1], 16;\n" :: "r"(smem), "l"(g));
}
#define CP_COMMIT()  asm volatile("cp.async.commit_group;\n" ::: "memory")
#define CP_WAIT_2()  asm volatile("cp.async.wait_group 2;\n" ::: "memory")
#define CP_WAIT_1()  asm volatile("cp.async.wait_group 1;\n" ::: "memory")
#define CP_WAIT_0()  asm volatile("cp.async.wait_group 0;\n" ::: "memory")

__device__ __forceinline__ float ex2(float x) {
    float y; asm("ex2.approx.ftz.f32 %0, %1;\n" : "=f"(y) : "f"(x)); return y;
}

__device__ __forceinline__ unsigned pack_h2(float a, float b) {
    __half2 h = __floats2half2_rn(a, b);
    return *(unsigned*)&h;
}

#define QSCALE (0.125f * 1.4426950408889634f)   // hd^-0.5 * log2(e)

// ---------------- fp16 conversion kernels ----------------
__global__ void __launch_bounds__(256) conv_x(const float* __restrict__ in) {
    int i = blockIdx.x * 256 + threadIdx.x;            // indexes float4
    float4 v = ((const float4*)in)[i];
    uint2 o;
    o.x = pack_h2(v.x, v.y);
    o.y = pack_h2(v.z, v.w);
    ((uint2*)g_xf)[i] = o;
}

// W [k][n] row-major -> fragment blocks g_wF[z][nb][ks][lane] (uint4 = 4 ldsm regs).
// Produced by replaying the exact smem-stage + ldmatrix path hgemm consumes.
__global__ void __launch_bounds__(256) conv_wF(
    const float* __restrict__ Wq, const float* __restrict__ Wk,
    const float* __restrict__ Wv, const float* __restrict__ Wo)
{
    const int z = blockIdx.z;
    const float* W = (z == 0) ? Wq : (z == 1) ? Wk : (z == 2) ? Wv : Wo;
    const int n0 = blockIdx.x * 128;      // 8 blocks
    const int k0 = blockIdx.y * 64;       // 16 blocks
    __shared__ __align__(16) char csm[4 * 6144];   // 4 k16 slabs, 128 rows x 48B
    const unsigned cb = (unsigned)__cvta_generic_to_shared(csm);
    const int tid = threadIdx.x;

    // stage transposed tile: smem[n][k] with 48B pitch per slab
    for (int i = 0; i < 32; i++) {
        int idx = tid + i * 256;              // (k, n): n contiguous -> coalesced
        int k = idx >> 7, n = idx & 127;
        float w = W[(size_t)(k0 + k) * DD + n0 + n];
        int slab = k >> 4, klo = k & 15;
        *(__half*)(csm + slab * 6144 + n * 48 + ((klo & 7) << 1) + ((klo >> 3) << 4)) =
            __float2half_rn(w);
    }
    __syncthreads();

    const int w = tid >> 5, lane = tid & 31;   // warp w -> n16 block w
#pragma unroll
    for (int s = 0; s < 4; s++) {
        unsigned bfr[4];
        unsigned addr = cb + s * 6144 +
            (unsigned)((w * 16 + ((lane >> 4) << 3) + (lane & 7)) * 48 +
                       (((lane >> 3) & 1) << 4));
        ldsm_x4(bfr, addr);
        uint4 o4; o4.x = bfr[0]; o4.y = bfr[1]; o4.z = bfr[2]; o4.w = bfr[3];
        g_wF[(((size_t)z * 64 + (n0 >> 4) + w) * 64 + (k0 >> 4) + s) * 32 + lane] = o4;
    }
}

// ---------------------------------------------------------------------------
// fp16 tensor-core GEMM: C tile 128x128, BK=32, 256 threads (8 warps of 64x32).
// A: 4-stage cp.async smem (12KB/stage). B: direct LDG.128 of pre-built
// fragments from L2, software-pipelined one iteration ahead. One barrier/iter.
// ---------------------------------------------------------------------------
#define SLAB_SZ  6144            // 128 rows * 48B (one k16 sub-slab)
#define STG_SZ   12288           // A only: 2 slabs
#define GM_SMEM  (4 * STG_SZ)    // 49152

__device__ __forceinline__ void gemm_prefetchA(
    unsigned sb, int stage, int k0,
    const __half* __restrict__ Af, int bm, int t)
{
    const unsigned base = sb + stage * STG_SZ;
#pragma unroll
    for (int r = 0; r < 2; r++) {                 // A: 512 x 16B
        int idx = t + 256 * r;
        int m = idx >> 2, q = idx & 3;
        int s = q >> 1, c = q & 1;
        cp16(base + s * SLAB_SZ + m * 48 + c * 16,
             Af + (size_t)(bm + m) * DD + k0 + s * 16 + c * 8);
    }
}

// MODE 0: QKV (z = blockIdx.z; q scaled; head-scatter epilogue, fp16 out)
// MODE 1: out projection (fp32 out + bias)
template<int MODE>
__global__ void __launch_bounds__(256, 2) hgemm(
    const float* __restrict__ biasA, const float* __restrict__ biasB,
    const float* __restrict__ biasC, float* __restrict__ outp)
{
    extern __shared__ __align__(16) char dsm[];
    const unsigned sb = (unsigned)__cvta_generic_to_shared(dsm);

    const int z = (MODE == 0) ? blockIdx.z : 3;
    const __half* Af = (MODE == 0) ? g_xf : g_cf;
    const float* bias = (MODE == 0) ? ((z == 0) ? biasA : (z == 1) ? biasB : biasC)
                                    : biasA;
    const float scale = (MODE == 0 && z == 0) ? QSCALE : 1.0f;

    const int t = threadIdx.x;
    const int bm = blockIdx.y << 7;
    const int bn = blockIdx.x << 7;
    const int wid = t >> 5, lane = t & 31;
    const int wm = (wid & 1) << 6;       // warp m offset
    const int wn = (wid >> 1) << 5;      // warp n offset

    float acc[4][4][4];
#pragma unroll
    for (int i = 0; i < 4; i++)
#pragma unroll
        for (int j = 0; j < 4; j++)
#pragma unroll
            for (int r = 0; r < 4; r++) acc[i][j][r] = 0.f;

    const unsigned a_row_off = (unsigned)((wm + (lane & 15)) * 48 + ((lane >> 4) << 4));

    // B fragment pointers: two n16 blocks for this warp's n32
    const uint4* b0p = g_wF + (((size_t)z * 64 + (bn >> 4) + (wn >> 4)) * 64) * 32 + lane;
    const uint4* b1p = b0p + 64 * 32;     // next n16 block

    gemm_prefetchA(sb, 0, 0,  Af, bm, t); CP_COMMIT();
    gemm_prefetchA(sb, 1, 32, Af, bm, t); CP_COMMIT();
    gemm_prefetchA(sb, 2, 64, Af, bm, t); CP_COMMIT();

    // B regs for iter 0 (slabs ks=0,1): [s*2 + nb]
    uint4 bc[4], bnx[4];
    bc[0] = b0p[0];  bc[1] = b1p[0];
    bc[2] = b0p[32]; bc[3] = b1p[32];

    const int NIT = DD / 32;   // 32 iterations of BK=32
    for (int it = 0; it < NIT; ++it) {
        if (it + 1 < NIT) {    // pipeline next iteration's B frags from L2
            const int ks = (it + 1) * 2;
            bnx[0] = b0p[(size_t)ks * 32];       bnx[1] = b1p[(size_t)ks * 32];
            bnx[2] = b0p[(size_t)(ks + 1) * 32]; bnx[3] = b1p[(size_t)(ks + 1) * 32];
        }

        if (it < NIT - 2)      { CP_WAIT_2(); }
        else if (it == NIT - 2){ CP_WAIT_1(); }
        else                   { CP_WAIT_0(); }
        __syncthreads();   // A stage 'it' ready; all warps done reading it-1

        const unsigned base = sb + (it & 3) * STG_SZ;
#pragma unroll
        for (int s = 0; s < 2; s++) {
            unsigned bfr[8];
            *(uint4*)(bfr)     = bc[s * 2];
            *(uint4*)(bfr + 4) = bc[s * 2 + 1];
            const unsigned abase = base + s * SLAB_SZ + a_row_off;
#pragma unroll
            for (int i = 0; i < 4; i++) {
                unsigned afr[4];
                ldsm_x4(afr, abase + i * 16 * 48);
#pragma unroll
                for (int j = 0; j < 4; j++)
                    mma_f16(acc[i][j], afr, bfr + 2 * j);
            }
        }

#pragma unroll
        for (int q = 0; q < 4; q++) bc[q] = bnx[q];

        if (it + 3 < NIT) {    // refill A buffer consumed at it-1
            gemm_prefetchA(sb, (it + 3) & 3, (it + 3) * 32, Af, bm, t);
            CP_COMMIT();
        }
    }

    // epilogue
    const int gg = lane >> 2, tg = lane & 3;
#pragma unroll
    for (int i = 0; i < 4; i++) {
#pragma unroll
        for (int j = 0; j < 4; j++) {
            const int row = bm + wm + 16 * i + gg;
            const int col = bn + wn + 8 * j + 2 * tg;
            float v00 = (acc[i][j][0] + bias[col])     * scale;
            float v01 = (acc[i][j][1] + bias[col + 1]) * scale;
            float v10 = (acc[i][j][2] + bias[col])     * scale;
            float v11 = (acc[i][j][3] + bias[col + 1]) * scale;
            if (MODE == 0) {
                const int head = col >> 6, d = col & 63;
                const int b0_ = row >> 11, t0_ = row & 2047;
                const int t1_ = (row + 8) & 2047;      // row+8 stays in same b
                const int bh_ = b0_ * 16 + head;
                if (z == 2) {
                    // vT: [bh][d][t]
                    size_t r0 = ((size_t)bh_ * 64 + d) * 2048;
                    size_t r1 = ((size_t)bh_ * 64 + d + 1) * 2048;
                    g_vTf[r0 + t0_] = __float2half_rn(v00);
                    g_vTf[r1 + t0_] = __float2half_rn(v01);
                    g_vTf[r0 + t1_] = __float2half_rn(v10);
                    g_vTf[r1 + t1_] = __float2half_rn(v11);
                } else {
                    __half* dst = (z == 0) ? g_qf : g_kf;
                    size_t o0 = ((size_t)bh_ * 2048 + t0_) * 64 + d;
                    size_t o1 = ((size_t)bh_ * 2048 + t1_) * 64 + d;
                    *(unsigned*)(dst + o0) = pack_h2(v00, v01);
                    *(unsigned*)(dst + o1) = pack_h2(v10, v11);
                }
            } else {
                outp[(size_t)row * DD + col]           = v00;
                outp[(size_t)row * DD + col + 1]       = v01;
                outp[(size_t)(row + 8) * DD + col]     = v10;
                outp[(size_t)(row + 8) * DD + col + 1] = v11;
            }
        }
    }
}

// ---------------------------------------------------------------------------
// fp16 tensor-core BD3LM attention (unchanged from R8 — 86.8us)
// ---------------------------------------------------------------------------
#define AT_PITCH  144
#define AT_ARR    (64 * AT_PITCH)     // 9216
#define AT_BUF    (2 * AT_ARR)        // 18432 (K, V)
#define AT_SMEM   (3 * AT_BUF)        // 55296

__global__ void __launch_bounds__(128, 4) attn_mma()
{
    extern __shared__ __align__(16) char dsm[];
    const unsigned sb = (unsigned)__cvta_generic_to_shared(dsm);

    const int bi = blockIdx.x;
    const int qt = (bi & 1) ? (31 - (bi >> 1)) : (15 - (bi >> 1));
    const int bh = blockIdx.y;
    const int qt0 = qt << 6;
    const int tid = threadIdx.x;
    const int lane = tid & 31, warp = tid >> 5;
    const int wm = warp << 4;
    const int g = lane >> 2, tq = lane & 3;

#pragma unroll
    for (int i = 0; i < 4; i++) {
        int idx = tid + (i << 7);
        int r = idx >> 3, c = idx & 7;
        cp16(sb + r * AT_PITCH + c * 16,
             g_qf + ((size_t)bh * 2048 + qt0 + r) * 64 + c * 8);
    }
    CP_COMMIT();
    CP_WAIT_0();
    __syncthreads();

    unsigned qf[4][4];
    const unsigned a_off = (unsigned)((wm + (lane & 15)) * AT_PITCH + ((lane >> 4) << 4));
#pragma unroll
    for (int c = 0; c < 4; c++)
        ldsm_x4(qf[c], sb + a_off + c * 32);
    __syncthreads();

    float o[8][4];
#pragma unroll
    for (int j = 0; j < 8; j++)
#pragma unroll
        for (int k = 0; k < 4; k++) o[j][k] = 0.f;
    float m0 = -1e30f, m1 = -1e30f, l0 = 0.f, l1 = 0.f;

    const bool is_x0 = (qt >= 16);
    const int nfull  = is_x0 ? (qt - 16) : qt;
    const int ntiles = nfull + (is_x0 ? 1 : 2);

    auto tile_of = [&](int it, int& s, int& mode) {
        if (it < nfull)        { s = 1024 + (it << 6); mode = 0; }
        else if (is_x0)        { s = qt0;              mode = 1; }
        else if (it == nfull)  { s = 1024 + qt0;       mode = 2; }
        else                   { s = qt0;              mode = 3; }
    };

    auto prefetch = [&](int s, int buf) {
        unsigned dstb = sb + buf * AT_BUF;
#pragma unroll
        for (int i = 0; i < 8; i++) {
            int idx = tid + (i << 7);
            int arr = idx >> 9, rem = idx & 511;
            int r = rem >> 3, c = rem & 7;
            const __half* src = (arr == 0)
                ? g_kf  + ((size_t)bh * 2048 + s + r) * 64 + c * 8
                : g_vTf + ((size_t)bh * 64 + r) * 2048 + s + c * 8;
            cp16(dstb + arr * AT_ARR + r * AT_PITCH + c * 16, src);
        }
    };

    {
        int s0, md; tile_of(0, s0, md);
        prefetch(s0, 0);
        CP_COMMIT();
        if (ntiles > 1) { int s1; tile_of(1, s1, md); prefetch(s1, 1); }
        CP_COMMIT();
    }

    const unsigned b_off = (unsigned)((((lane >> 4) << 3) + (lane & 7)) * AT_PITCH +
                                      (((lane >> 3) & 1) << 4));

    for (int it = 0; it < ntiles; ++it) {
        int s_, mode; tile_of(it, s_, mode);
        if (it < ntiles - 1) { CP_WAIT_1(); } else { CP_WAIT_0(); }
        __syncthreads();

        const unsigned base = sb + (it % 3) * AT_BUF;

        float sc[8][4];
#pragma unroll
        for (int j = 0; j < 8; j++)
#pragma unroll
            for (int k = 0; k < 4; k++) sc[j][k] = 0.f;

#pragma unroll
        for (int c = 0; c < 4; c++) {
#pragma unroll
            for (int p = 0; p < 4; p++) {
                unsigned kb[4];
                ldsm_x4(kb, base + (p << 4) * AT_PITCH + b_off + c * 32);
                mma_f16(sc[2 * p],     qf[c], kb);
                mma_f16(sc[2 * p + 1], qf[c], kb + 2);
            }
        }

        if (mode) {
#pragma unroll
            for (int j = 0; j < 8; j++)
#pragma unroll
                for (int k = 0; k < 4; k++) {
                    int r = wm + g + ((k >> 1) << 3);
                    int c = (j << 3) + (tq << 1) + (k & 1);
                    int r2 = r >> 2, c2 = c >> 2;
                    bool ok = (mode == 1) ? (c2 <= r2) :
                              (mode == 2) ? (c2 <  r2) : (c2 == r2);
                    if (!ok) sc[j][k] = -1e30f;
                }
        }

        float t0 = -1e30f, t1 = -1e30f;
#pragma unroll
        for (int j = 0; j < 8; j++) {
            t0 = fmaxf(t0, fmaxf(sc[j][0], sc[j][1]));
            t1 = fmaxf(t1, fmaxf(sc[j][2], sc[j][3]));
        }
        t0 = fmaxf(t0, __shfl_xor_sync(0xffffffffu, t0, 1));
        t0 = fmaxf(t0, __shfl_xor_sync(0xffffffffu, t0, 2));
        t1 = fmaxf(t1, __shfl_xor_sync(0xffffffffu, t1, 1));
        t1 = fmaxf(t1, __shfl_xor_sync(0xffffffffu, t1, 2));
        const float mn0 = fmaxf(m0, t0), mn1 = fmaxf(m1, t1);
        const float r0 = ex2(m0 - mn0), r1 = ex2(m1 - mn1);
        float ls0 = 0.f, ls1 = 0.f;
#pragma unroll
        for (int j = 0; j < 8; j++) {
            sc[j][0] = ex2(sc[j][0] - mn0);
            sc[j][1] = ex2(sc[j][1] - mn0);
            sc[j][2] = ex2(sc[j][2] - mn1);
            sc[j][3] = ex2(sc[j][3] - mn1);
            ls0 += sc[j][0] + sc[j][1];
            ls1 += sc[j][2] + sc[j][3];
        }
        ls0 += __shfl_xor_sync(0xffffffffu, ls0, 1);
        ls0 += __shfl_xor_sync(0xffffffffu, ls0, 2);
        ls1 += __shfl_xor_sync(0xffffffffu, ls1, 1);
        ls1 += __shfl_xor_sync(0xffffffffu, ls1, 2);
        l0 = l0 * r0 + ls0;  m0 = mn0;
        l1 = l1 * r1 + ls1;  m1 = mn1;
#pragma unroll
        for (int j = 0; j < 8; j++) {
            o[j][0] *= r0; o[j][1] *= r0;
            o[j][2] *= r1; o[j][3] *= r1;
        }

#pragma unroll
        for (int c = 0; c < 4; c++) {
            unsigned pf[4];
            pf[0] = pack_h2(sc[2 * c][0],     sc[2 * c][1]);
            pf[1] = pack_h2(sc[2 * c][2],     sc[2 * c][3]);
            pf[2] = pack_h2(sc[2 * c + 1][0], sc[2 * c + 1][1]);
            pf[3] = pack_h2(sc[2 * c + 1][2], sc[2 * c + 1][3]);
#pragma unroll
            for (int p = 0; p < 4; p++) {
                unsigned vb[4];
                ldsm_x4(vb, base + AT_ARR + (p << 4) * AT_PITCH + b_off + c * 32);
                mma_f16(o[2 * p],     pf, vb);
                mma_f16(o[2 * p + 1], pf, vb + 2);
            }
        }

        if (it + 2 < ntiles) {
            int sn, mn; tile_of(it + 2, sn, mn);
            prefetch(sn, (it + 2) % 3);
            CP_COMMIT();
        }
    }

    const float inv0 = 1.f / l0, inv1 = 1.f / l1;
    const int b_ = bh >> 4, h_ = bh & 15;
    const int row0 = qt0 + wm + g;
    __half* c0 = g_cf + ((size_t)b_ * 2048 + row0) * 1024 + h_ * 64 + (tq << 1);
#pragma unroll
    for (int j = 0; j < 8; j++) {
        *(unsigned*)(c0 + (j << 3)) = pack_h2(o[j][0] * inv0, o[j][1] * inv0);
        *(unsigned*)(c0 + 8 * 1024 + (j << 3)) = pack_h2(o[j][2] * inv1, o[j][3] * inv1);
    }
}

// ---------------------------------------------------------------------------

extern "C" void kernel_launch(void* const* d_in, const int* in_sizes, int n_in,
                              void* d_out, int out_size)
{
    const float* x  = (const float*)d_in[0];
    const float* Wq = (const float*)d_in[1];
    const float* bq = (const float*)d_in[2];
    const float* Wk = (const float*)d_in[3];
    const float* bk = (const float*)d_in[4];
    const float* Wv = (const float*)d_in[5];
    const float* bv = (const float*)d_in[6];
    const float* Wo = (const float*)d_in[7];
    const float* bo = (const float*)d_in[8];

    cudaFuncSetAttribute(hgemm<0>, cudaFuncAttributeMaxDynamicSharedMemorySize, GM_SMEM);
    cudaFuncSetAttribute(hgemm<1>, cudaFuncAttributeMaxDynamicSharedMemorySize, GM_SMEM);
    cudaFuncSetAttribute(attn_mma, cudaFuncAttributeMaxDynamicSharedMemorySize, AT_SMEM);

    conv_x<<<(MROWS * DD / 4) / 256, 256>>>(x);
    conv_wF<<<dim3(8, 16, 4), 256>>>(Wq, Wk, Wv, Wo);

    hgemm<0><<<dim3(8, 64, 3), 256, GM_SMEM>>>(bq, bk, bv, nullptr);

    attn_mma<<<dim3(32, 64), 128, AT_SMEM>>>();

    hgemm<1><<<dim3(8, 64), 256, GM_SMEM>>>(bo, nullptr, nullptr, (float*)d_out);
}

// round 13
// speedup vs baseline: 18.4376x; 1.0131x over previous
#include <cuda_runtime.h>
#include <cuda_fp16.h>
#include <cstdint>

// Problem constants (fixed by setup_inputs)
#define TT    2048
#define DD    1024
#define HH    16
#define HDIM  64
#define BB    4
#define NBH   64        // B*H
#define MROWS 8192      // B*T

// ---------------- scratch (no cudaMalloc allowed) ----------------
__device__ __align__(16) __half g_xf[(size_t)MROWS * DD];          // x fp16
__device__ uint4 g_wF[(size_t)4 * 64 * 64 * 32];                   // W fragment blocks [z][nb][ks][lane]
__device__ __align__(16) __half g_qf[(size_t)NBH * TT * HDIM];     // [bh][t][d]
__device__ __align__(16) __half g_kf[(size_t)NBH * TT * HDIM];
__device__ __align__(16) __half g_vTf[(size_t)NBH * HDIM * TT];    // [bh][d][t]
__device__ __align__(16) __half g_cf[(size_t)MROWS * DD];          // ctx fp16

// ---------------- PTX helpers ----------------
__device__ __forceinline__ void mma_f16(float* c, const unsigned* a, const unsigned* b) {
    asm volatile(
        "mma.sync.aligned.m16n8k16.row.col.f32.f16.f16.f32 "
        "{%0,%1,%2,%3}, {%4,%5,%6,%7}, {%8,%9}, {%0,%1,%2,%3};\n"
        : "+f"(c[0]), "+f"(c[1]), "+f"(c[2]), "+f"(c[3])
        : "r"(a[0]), "r"(a[1]), "r"(a[2]), "r"(a[3]), "r"(b[0]), "r"(b[1]));
}

__device__ __forceinline__ void ldsm_x4(unsigned* r, unsigned addr) {
    asm volatile("ldmatrix.sync.aligned.m8n8.x4.shared.b16 {%0,%1,%2,%3}, [%4];\n"
                 : "=r"(r[0]), "=r"(r[1]), "=r"(r[2]), "=r"(r[3]) : "r"(addr));
}

__device__ __forceinline__ void cp16(unsigned smem, const void* g) {
    asm volatile("cp.async.ca.shared.global [%0], [%1], 16;\n" :: "r"(smem), "l"(g));
}
#define CP_COMMIT()  asm volatile("cp.async.commit_group;\n" ::: "memory")
#define CP_WAIT_2()  asm volatile("cp.async.wait_group 2;\n" ::: "memory")
#define CP_WAIT_1()  asm volatile("cp.async.wait_group 1;\n" ::: "memory")
#define CP_WAIT_0()  asm volatile("cp.async.wait_group 0;\n" ::: "memory")

__device__ __forceinline__ float ex2(float x) {
    float y; asm("ex2.approx.ftz.f32 %0, %1;\n" : "=f"(y) : "f"(x)); return y;
}

// packed fp16x2 exp2
__device__ __forceinline__ unsigned h2ex2(unsigned x) {
    unsigned y; asm("ex2.approx.f16x2 %0, %1;\n" : "=r"(y) : "r"(x)); return y;
}

__device__ __forceinline__ unsigned pack_h2(float a, float b) {
    __half2 h = __floats2half2_rn(a, b);
    return *(unsigned*)&h;
}

#define QSCALE (0.125f * 1.4426950408889634f)   // hd^-0.5 * log2(e)

// ---------------- fp16 conversion kernels ----------------
__global__ void __launch_bounds__(256) conv_x(const float* __restrict__ in) {
    int i = blockIdx.x * 256 + threadIdx.x;            // indexes float4
    float4 v = ((const float4*)in)[i];
    uint2 o;
    o.x = pack_h2(v.x, v.y);
    o.y = pack_h2(v.z, v.w);
    ((uint2*)g_xf)[i] = o;
}

// W [k][n] row-major -> fragment blocks g_wF[z][nb][ks][lane] (uint4 = 4 ldsm regs).
// Produced by replaying the exact smem-stage + ldmatrix path hgemm consumes.
__global__ void __launch_bounds__(256) conv_wF(
    const float* __restrict__ Wq, const float* __restrict__ Wk,
    const float* __restrict__ Wv, const float* __restrict__ Wo)
{
    const int z = blockIdx.z;
    const float* W = (z == 0) ? Wq : (z == 1) ? Wk : (z == 2) ? Wv : Wo;
    const int n0 = blockIdx.x * 128;      // 8 blocks
    const int k0 = blockIdx.y * 64;       // 16 blocks
    __shared__ __align__(16) char csm[4 * 6144];   // 4 k16 slabs, 128 rows x 48B
    const unsigned cb = (unsigned)__cvta_generic_to_shared(csm);
    const int tid = threadIdx.x;

    // stage transposed tile: smem[n][k] with 48B pitch per slab
    for (int i = 0; i < 32; i++) {
        int idx = tid + i * 256;              // (k, n): n contiguous -> coalesced
        int k = idx >> 7, n = idx & 127;
        float w = W[(size_t)(k0 + k) * DD + n0 + n];
        int slab = k >> 4, klo = k & 15;
        *(__half*)(csm + slab * 6144 + n * 48 + ((klo & 7) << 1) + ((klo >> 3) << 4)) =
            __float2half_rn(w);
    }
    __syncthreads();

    const int w = tid >> 5, lane = tid & 31;   // warp w -> n16 block w
#pragma unroll
    for (int s = 0; s < 4; s++) {
        unsigned bfr[4];
        unsigned addr = cb + s * 6144 +
            (unsigned)((w * 16 + ((lane >> 4) << 3) + (lane & 7)) * 48 +
                       (((lane >> 3) & 1) << 4));
        ldsm_x4(bfr, addr);
        uint4 o4; o4.x = bfr[0]; o4.y = bfr[1]; o4.z = bfr[2]; o4.w = bfr[3];
        g_wF[(((size_t)z * 64 + (n0 >> 4) + w) * 64 + (k0 >> 4) + s) * 32 + lane] = o4;
    }
}

// ---------------------------------------------------------------------------
// fp16 tensor-core GEMM: C tile 128x128, BK=32, 256 threads (8 warps of 64x32).
// A: 4-stage cp.async smem (12KB/stage). B: direct LDG.128 of pre-built
// fragments from L2, software-pipelined one iteration ahead. One barrier/iter.
// ---------------------------------------------------------------------------
#define SLAB_SZ  6144            // 128 rows * 48B (one k16 sub-slab)
#define STG_SZ   12288           // A only: 2 slabs
#define GM_SMEM  (4 * STG_SZ)    // 49152

__device__ __forceinline__ void gemm_prefetchA(
    unsigned sb, int stage, int k0,
    const __half* __restrict__ Af, int bm, int t)
{
    const unsigned base = sb + stage * STG_SZ;
#pragma unroll
    for (int r = 0; r < 2; r++) {                 // A: 512 x 16B
        int idx = t + 256 * r;
        int m = idx >> 2, q = idx & 3;
        int s = q >> 1, c = q & 1;
        cp16(base + s * SLAB_SZ + m * 48 + c * 16,
             Af + (size_t)(bm + m) * DD + k0 + s * 16 + c * 8);
    }
}

// MODE 0: QKV (z = blockIdx.z; q scaled; head-scatter epilogue, fp16 out)
// MODE 1: out projection (fp32 out + bias)
template<int MODE>
__global__ void __launch_bounds__(256, 2) hgemm(
    const float* __restrict__ biasA, const float* __restrict__ biasB,
    const float* __restrict__ biasC, float* __restrict__ outp)
{
    extern __shared__ __align__(16) char dsm[];
    const unsigned sb = (unsigned)__cvta_generic_to_shared(dsm);

    const int z = (MODE == 0) ? blockIdx.z : 3;
    const __half* Af = (MODE == 0) ? g_xf : g_cf;
    const float* bias = (MODE == 0) ? ((z == 0) ? biasA : (z == 1) ? biasB : biasC)
                                    : biasA;
    const float scale = (MODE == 0 && z == 0) ? QSCALE : 1.0f;

    const int t = threadIdx.x;
    const int bm = blockIdx.y << 7;
    const int bn = blockIdx.x << 7;
    const int wid = t >> 5, lane = t & 31;
    const int wm = (wid & 1) << 6;       // warp m offset
    const int wn = (wid >> 1) << 5;      // warp n offset

    float acc[4][4][4];
#pragma unroll
    for (int i = 0; i < 4; i++)
#pragma unroll
        for (int j = 0; j < 4; j++)
#pragma unroll
            for (int r = 0; r < 4; r++) acc[i][j][r] = 0.f;

    const unsigned a_row_off = (unsigned)((wm + (lane & 15)) * 48 + ((lane >> 4) << 4));

    // B fragment pointers: two n16 blocks for this warp's n32
    const uint4* b0p = g_wF + (((size_t)z * 64 + (bn >> 4) + (wn >> 4)) * 64) * 32 + lane;
    const uint4* b1p = b0p + 64 * 32;     // next n16 block

    gemm_prefetchA(sb, 0, 0,  Af, bm, t); CP_COMMIT();
    gemm_prefetchA(sb, 1, 32, Af, bm, t); CP_COMMIT();
    gemm_prefetchA(sb, 2, 64, Af, bm, t); CP_COMMIT();

    // B regs for iter 0 (slabs ks=0,1): [s*2 + nb]
    uint4 bc[4], bnx[4];
    bc[0] = b0p[0];  bc[1] = b1p[0];
    bc[2] = b0p[32]; bc[3] = b1p[32];

    const int NIT = DD / 32;   // 32 iterations of BK=32
    for (int it = 0; it < NIT; ++it) {
        if (it + 1 < NIT) {    // pipeline next iteration's B frags from L2
            const int ks = (it + 1) * 2;
            bnx[0] = b0p[(size_t)ks * 32];       bnx[1] = b1p[(size_t)ks * 32];
            bnx[2] = b0p[(size_t)(ks + 1) * 32]; bnx[3] = b1p[(size_t)(ks + 1) * 32];
        }

        if (it < NIT - 2)      { CP_WAIT_2(); }
        else if (it == NIT - 2){ CP_WAIT_1(); }
        else                   { CP_WAIT_0(); }
        __syncthreads();   // A stage 'it' ready; all warps done reading it-1

        const unsigned base = sb + (it & 3) * STG_SZ;
#pragma unroll
        for (int s = 0; s < 2; s++) {
            unsigned bfr[8];
            *(uint4*)(bfr)     = bc[s * 2];
            *(uint4*)(bfr + 4) = bc[s * 2 + 1];
            const unsigned abase = base + s * SLAB_SZ + a_row_off;
#pragma unroll
            for (int i = 0; i < 4; i++) {
                unsigned afr[4];
                ldsm_x4(afr, abase + i * 16 * 48);
#pragma unroll
                for (int j = 0; j < 4; j++)
                    mma_f16(acc[i][j], afr, bfr + 2 * j);
            }
        }

#pragma unroll
        for (int q = 0; q < 4; q++) bc[q] = bnx[q];

        if (it + 3 < NIT) {    // refill A buffer consumed at it-1
            gemm_prefetchA(sb, (it + 3) & 3, (it + 3) * 32, Af, bm, t);
            CP_COMMIT();
        }
    }

    // epilogue
    const int gg = lane >> 2, tg = lane & 3;
#pragma unroll
    for (int i = 0; i < 4; i++) {
#pragma unroll
        for (int j = 0; j < 4; j++) {
            const int row = bm + wm + 16 * i + gg;
            const int col = bn + wn + 8 * j + 2 * tg;
            float v00 = (acc[i][j][0] + bias[col])     * scale;
            float v01 = (acc[i][j][1] + bias[col + 1]) * scale;
            float v10 = (acc[i][j][2] + bias[col])     * scale;
            float v11 = (acc[i][j][3] + bias[col + 1]) * scale;
            if (MODE == 0) {
                const int head = col >> 6, d = col & 63;
                const int b0_ = row >> 11, t0_ = row & 2047;
                const int t1_ = (row + 8) & 2047;      // row+8 stays in same b
                const int bh_ = b0_ * 16 + head;
                if (z == 2) {
                    // vT: [bh][d][t]
                    size_t r0 = ((size_t)bh_ * 64 + d) * 2048;
                    size_t r1 = ((size_t)bh_ * 64 + d + 1) * 2048;
                    g_vTf[r0 + t0_] = __float2half_rn(v00);
                    g_vTf[r1 + t0_] = __float2half_rn(v01);
                    g_vTf[r0 + t1_] = __float2half_rn(v10);
                    g_vTf[r1 + t1_] = __float2half_rn(v11);
                } else {
                    __half* dst = (z == 0) ? g_qf : g_kf;
                    size_t o0 = ((size_t)bh_ * 2048 + t0_) * 64 + d;
                    size_t o1 = ((size_t)bh_ * 2048 + t1_) * 64 + d;
                    *(unsigned*)(dst + o0) = pack_h2(v00, v01);
                    *(unsigned*)(dst + o1) = pack_h2(v10, v11);
                }
            } else {
                outp[(size_t)row * DD + col]           = v00;
                outp[(size_t)row * DD + col + 1]       = v01;
                outp[(size_t)(row + 8) * DD + col]     = v10;
                outp[(size_t)(row + 8) * DD + col + 1] = v11;
            }
        }
    }
}

// ---------------------------------------------------------------------------
// fp16 tensor-core BD3LM attention. Block = (bh, 64-row q-tile), 128 threads
// (4 warps, each m16 x n64). K tiles [kv][64], V^T tiles [d][kv], 144B pitch.
// 3 KV buffers, ONE barrier per tile. Softmax: fp16x2 exp; row-sum l obtained
// from an all-ones n8 mma accumulated alongside O (osum == l at the end).
// ---------------------------------------------------------------------------
#define AT_PITCH  144
#define AT_ARR    (64 * AT_PITCH)     // 9216
#define AT_BUF    (2 * AT_ARR)        // 18432 (K, V)
#define AT_SMEM   (3 * AT_BUF)        // 55296

__global__ void __launch_bounds__(128, 4) attn_mma()
{
    extern __shared__ __align__(16) char dsm[];
    const unsigned sb = (unsigned)__cvta_generic_to_shared(dsm);

    const int bi = blockIdx.x;
    const int qt = (bi & 1) ? (31 - (bi >> 1)) : (15 - (bi >> 1));
    const int bh = blockIdx.y;
    const int qt0 = qt << 6;
    const int tid = threadIdx.x;
    const int lane = tid & 31, warp = tid >> 5;
    const int wm = warp << 4;
    const int g = lane >> 2, tq = lane & 3;

#pragma unroll
    for (int i = 0; i < 4; i++) {
        int idx = tid + (i << 7);
        int r = idx >> 3, c = idx & 7;
        cp16(sb + r * AT_PITCH + c * 16,
             g_qf + ((size_t)bh * 2048 + qt0 + r) * 64 + c * 8);
    }
    CP_COMMIT();
    CP_WAIT_0();
    __syncthreads();

    unsigned qf[4][4];
    const unsigned a_off = (unsigned)((wm + (lane & 15)) * AT_PITCH + ((lane >> 4) << 4));
#pragma unroll
    for (int c = 0; c < 4; c++)
        ldsm_x4(qf[c], sb + a_off + c * 32);
    __syncthreads();

    float o[8][4];
#pragma unroll
    for (int j = 0; j < 8; j++)
#pragma unroll
        for (int k = 0; k < 4; k++) o[j][k] = 0.f;
    float osum[4] = {0.f, 0.f, 0.f, 0.f};   // all-ones column: becomes l
    float m0 = -1e30f, m1 = -1e30f;

    const bool is_x0 = (qt >= 16);
    const int nfull  = is_x0 ? (qt - 16) : qt;
    const int ntiles = nfull + (is_x0 ? 1 : 2);

    auto tile_of = [&](int it, int& s, int& mode) {
        if (it < nfull)        { s = 1024 + (it << 6); mode = 0; }
        else if (is_x0)        { s = qt0;              mode = 1; }
        else if (it == nfull)  { s = 1024 + qt0;       mode = 2; }
        else                   { s = qt0;              mode = 3; }
    };

    auto prefetch = [&](int s, int buf) {
        unsigned dstb = sb + buf * AT_BUF;
#pragma unroll
        for (int i = 0; i < 8; i++) {
            int idx = tid + (i << 7);
            int arr = idx >> 9, rem = idx & 511;
            int r = rem >> 3, c = rem & 7;
            const __half* src = (arr == 0)
                ? g_kf  + ((size_t)bh * 2048 + s + r) * 64 + c * 8
                : g_vTf + ((size_t)bh * 64 + r) * 2048 + s + c * 8;
            cp16(dstb + arr * AT_ARR + r * AT_PITCH + c * 16, src);
        }
    };

    {
        int s0, md; tile_of(0, s0, md);
        prefetch(s0, 0);
        CP_COMMIT();
        if (ntiles > 1) { int s1; tile_of(1, s1, md); prefetch(s1, 1); }
        CP_COMMIT();
    }

    const unsigned b_off = (unsigned)((((lane >> 4) << 3) + (lane & 7)) * AT_PITCH +
                                      (((lane >> 3) & 1) << 4));
    const unsigned onesb[2] = {0x3C003C00u, 0x3C003C00u};   // fp16 1.0 x4

    for (int it = 0; it < ntiles; ++it) {
        int s_, mode; tile_of(it, s_, mode);
        if (it < ntiles - 1) { CP_WAIT_1(); } else { CP_WAIT_0(); }
        __syncthreads();

        const unsigned base = sb + (it % 3) * AT_BUF;

        // ---- S = Q K^T ----
        float sc[8][4];
#pragma unroll
        for (int j = 0; j < 8; j++)
#pragma unroll
            for (int k = 0; k < 4; k++) sc[j][k] = 0.f;

#pragma unroll
        for (int c = 0; c < 4; c++) {
#pragma unroll
            for (int p = 0; p < 4; p++) {
                unsigned kb[4];
                ldsm_x4(kb, base + (p << 4) * AT_PITCH + b_off + c * 32);
                mma_f16(sc[2 * p],     qf[c], kb);
                mma_f16(sc[2 * p + 1], qf[c], kb + 2);
            }
        }

        // ---- mask (boundary tiles only): block index = idx>>2 ----
        if (mode) {
#pragma unroll
            for (int j = 0; j < 8; j++)
#pragma unroll
                for (int k = 0; k < 4; k++) {
                    int r = wm + g + ((k >> 1) << 3);
                    int c = (j << 3) + (tq << 1) + (k & 1);
                    int r2 = r >> 2, c2 = c >> 2;
                    bool ok = (mode == 1) ? (c2 <= r2) :
                              (mode == 2) ? (c2 <  r2) : (c2 == r2);
                    if (!ok) sc[j][k] = -1e30f;
                }
        }

        // ---- online softmax: max (fp32) then fp16x2 exp -> P fragments ----
        float t0 = -1e30f, t1 = -1e30f;
#pragma unroll
        for (int j = 0; j < 8; j++) {
            t0 = fmaxf(t0, fmaxf(sc[j][0], sc[j][1]));
            t1 = fmaxf(t1, fmaxf(sc[j][2], sc[j][3]));
        }
        t0 = fmaxf(t0, __shfl_xor_sync(0xffffffffu, t0, 1));
        t0 = fmaxf(t0, __shfl_xor_sync(0xffffffffu, t0, 2));
        t1 = fmaxf(t1, __shfl_xor_sync(0xffffffffu, t1, 1));
        t1 = fmaxf(t1, __shfl_xor_sync(0xffffffffu, t1, 2));
        const float mn0 = fmaxf(m0, t0), mn1 = fmaxf(m1, t1);
        const float r0 = ex2(m0 - mn0), r1 = ex2(m1 - mn1);
        m0 = mn0; m1 = mn1;

        unsigned ph[8], pl[8];   // P fp16x2: rows g / g+8
#pragma unroll
        for (int j = 0; j < 8; j++) {
            ph[j] = h2ex2(pack_h2(sc[j][0] - mn0, sc[j][1] - mn0));
            pl[j] = h2ex2(pack_h2(sc[j][2] - mn1, sc[j][3] - mn1));
        }

        // rescale accumulators (osum follows the same recurrence -> final l)
#pragma unroll
        for (int j = 0; j < 8; j++) {
            o[j][0] *= r0; o[j][1] *= r0;
            o[j][2] *= r1; o[j][3] *= r1;
        }
        osum[0] *= r0; osum[1] *= r0;
        osum[2] *= r1; osum[3] *= r1;

        // ---- O += P V ; osum += P @ ones ----
#pragma unroll
        for (int c = 0; c < 4; c++) {
            unsigned pf[4];
            pf[0] = ph[2 * c];     pf[1] = pl[2 * c];
            pf[2] = ph[2 * c + 1]; pf[3] = pl[2 * c + 1];
            mma_f16(osum, pf, onesb);
#pragma unroll
            for (int p = 0; p < 4; p++) {
                unsigned vb[4];
                ldsm_x4(vb, base + AT_ARR + (p << 4) * AT_PITCH + b_off + c * 32);
                mma_f16(o[2 * p],     pf, vb);
                mma_f16(o[2 * p + 1], pf, vb + 2);
            }
        }

        if (it + 2 < ntiles) {
            int sn, mn; tile_of(it + 2, sn, mn);
            prefetch(sn, (it + 2) % 3);
            CP_COMMIT();
        }
    }

    // ---- epilogue: normalize by osum (== l), store ctx fp16 ----
    const float inv0 = 1.f / osum[0], inv1 = 1.f / osum[2];
    const int b_ = bh >> 4, h_ = bh & 15;
    const int row0 = qt0 + wm + g;
    __half* c0 = g_cf + ((size_t)b_ * 2048 + row0) * 1024 + h_ * 64 + (tq << 1);
#pragma unroll
    for (int j = 0; j < 8; j++) {
        *(unsigned*)(c0 + (j << 3)) = pack_h2(o[j][0] * inv0, o[j][1] * inv0);
        *(unsigned*)(c0 + 8 * 1024 + (j << 3)) = pack_h2(o[j][2] * inv1, o[j][3] * inv1);
    }
}

// ---------------------------------------------------------------------------

extern "C" void kernel_launch(void* const* d_in, const int* in_sizes, int n_in,
                              void* d_out, int out_size)
{
    const float* x  = (const float*)d_in[0];
    const float* Wq = (const float*)d_in[1];
    const float* bq = (const float*)d_in[2];
    const float* Wk = (const float*)d_in[3];
    const float* bk = (const float*)d_in[4];
    const float* Wv = (const float*)d_in[5];
    const float* bv = (const float*)d_in[6];
    const float* Wo = (const float*)d_in[7];
    const float* bo = (const float*)d_in[8];

    cudaFuncSetAttribute(hgemm<0>, cudaFuncAttributeMaxDynamicSharedMemorySize, GM_SMEM);
    cudaFuncSetAttribute(hgemm<1>, cudaFuncAttributeMaxDynamicSharedMemorySize, GM_SMEM);
    cudaFuncSetAttribute(attn_mma, cudaFuncAttributeMaxDynamicSharedMemorySize, AT_SMEM);

    conv_x<<<(MROWS * DD / 4) / 256, 256>>>(x);
    conv_wF<<<dim3(8, 16, 4), 256>>>(Wq, Wk, Wv, Wo);

    hgemm<0><<<dim3(8, 64, 3), 256, GM_SMEM>>>(bq, bk, bv, nullptr);

    attn_mma<<<dim3(32, 64), 128, AT_SMEM>>>();

    hgemm<1><<<dim3(8, 64), 256, GM_SMEM>>>(bo, nullptr, nullptr, (float*)d_out);
}

// round 14
// speedup vs baseline: 20.8333x; 1.1299x over previous
#include <cuda_runtime.h>
#include <cuda_fp16.h>
#include <cstdint>

// Problem constants (fixed by setup_inputs)
#define TT    2048
#define DD    1024
#define HH    16
#define HDIM  64
#define BB    4
#define NBH   64        // B*H
#define MROWS 8192      // B*T

// ---------------- scratch (no cudaMalloc allowed) ----------------
__device__ uint4 g_aF[(size_t)512 * 64 * 32];                      // A fragment blocks [mb][ks][lane]
__device__ uint4 g_wF[(size_t)4 * 64 * 64 * 32];                   // W fragment blocks [z][nb][ks][lane]
__device__ __align__(16) __half g_qf[(size_t)NBH * TT * HDIM];     // [bh][t][d]
__device__ __align__(16) __half g_kf[(size_t)NBH * TT * HDIM];
__device__ __align__(16) __half g_vTf[(size_t)NBH * HDIM * TT];    // [bh][d][t]
__device__ __align__(16) __half g_cf[(size_t)MROWS * DD];          // ctx fp16

// ---------------- PTX helpers ----------------
__device__ __forceinline__ void mma_f16(float* c, const unsigned* a, const unsigned* b) {
    asm volatile(
        "mma.sync.aligned.m16n8k16.row.col.f32.f16.f16.f32 "
        "{%0,%1,%2,%3}, {%4,%5,%6,%7}, {%8,%9}, {%0,%1,%2,%3};\n"
        : "+f"(c[0]), "+f"(c[1]), "+f"(c[2]), "+f"(c[3])
        : "r"(a[0]), "r"(a[1]), "r"(a[2]), "r"(a[3]), "r"(b[0]), "r"(b[1]));
}

__device__ __forceinline__ void ldsm_x4(unsigned* r, unsigned addr) {
    asm volatile("ldmatrix.sync.aligned.m8n8.x4.shared.b16 {%0,%1,%2,%3}, [%4];\n"
                 : "=r"(r[0]), "=r"(r[1]), "=r"(r[2]), "=r"(r[3]) : "r"(addr));
}

__device__ __forceinline__ void cp16(unsigned smem, const void* g) {
    asm volatile("cp.async.ca.shared.global [%0], [%1], 16;\n" :: "r"(smem), "l"(g));
}
#define CP_COMMIT()  asm volatile("cp.async.commit_group;\n" ::: "memory")
#define CP_WAIT_1()  asm volatile("cp.async.wait_group 1;\n" ::: "memory")
#define CP_WAIT_0()  asm volatile("cp.async.wait_group 0;\n" ::: "memory")

__device__ __forceinline__ float ex2(float x) {
    float y; asm("ex2.approx.ftz.f32 %0, %1;\n" : "=f"(y) : "f"(x)); return y;
}

// packed fp16x2 exp2
__device__ __forceinline__ unsigned h2ex2(unsigned x) {
    unsigned y; asm("ex2.approx.f16x2 %0, %1;\n" : "=r"(y) : "r"(x)); return y;
}

__device__ __forceinline__ unsigned pack_h2(float a, float b) {
    __half2 h = __floats2half2_rn(a, b);
    return *(unsigned*)&h;
}

#define QSCALE (0.125f * 1.4426950408889634f)   // hd^-0.5 * log2(e)

// ---------------- fragment-builder kernels ----------------
// A [m][k] (fp32 x for SRC=0, fp16 ctx for SRC=1) -> A fragment blocks
// g_aF[mb][ks][lane], produced by replaying hgemm's A smem-stage + ldsm pattern.
template<int SRC>
__global__ void __launch_bounds__(256) conv_aF(const float* __restrict__ xin) {
    const int m0 = blockIdx.x * 128;
    const int k0 = blockIdx.y * 64;
    __shared__ __align__(16) char csm[4 * 6144];   // 4 k16 slabs, 128 rows x 48B
    const unsigned cb = (unsigned)__cvta_generic_to_shared(csm);
    const int tid = threadIdx.x;

    // stage: smem[slab][m*48 + packed k] (identical byte layout to hgemm's A stage)
    for (int i = 0; i < 32; i++) {
        int idx = tid + i * 256;              // 128m x 64k
        int m = idx >> 6, k = idx & 63;
        __half h;
        if (SRC == 0) h = __float2half_rn(xin[(size_t)(m0 + m) * DD + k0 + k]);
        else          h = g_cf[(size_t)(m0 + m) * DD + k0 + k];
        int slab = k >> 4, klo = k & 15;
        *(__half*)(csm + slab * 6144 + m * 48 + ((klo & 7) << 1) + ((klo >> 3) << 4)) = h;
    }
    __syncthreads();

    const int w = tid >> 5, lane = tid & 31;   // warp w -> m16 block w
#pragma unroll
    for (int s = 0; s < 4; s++) {
        unsigned afr[4];
        unsigned addr = cb + s * 6144 +
            (unsigned)((w * 16 + (lane & 15)) * 48 + ((lane >> 4) << 4));
        ldsm_x4(afr, addr);
        uint4 o4; o4.x = afr[0]; o4.y = afr[1]; o4.z = afr[2]; o4.w = afr[3];
        g_aF[(((size_t)(m0 >> 4) + w) * 64 + (k0 >> 4) + s) * 32 + lane] = o4;
    }
}

// W [k][n] row-major -> fragment blocks g_wF[z][nb][ks][lane] (uint4 = 4 ldsm regs).
__global__ void __launch_bounds__(256) conv_wF(
    const float* __restrict__ Wq, const float* __restrict__ Wk,
    const float* __restrict__ Wv, const float* __restrict__ Wo)
{
    const int z = blockIdx.z;
    const float* W = (z == 0) ? Wq : (z == 1) ? Wk : (z == 2) ? Wv : Wo;
    const int n0 = blockIdx.x * 128;      // 8 blocks
    const int k0 = blockIdx.y * 64;       // 16 blocks
    __shared__ __align__(16) char csm[4 * 6144];
    const unsigned cb = (unsigned)__cvta_generic_to_shared(csm);
    const int tid = threadIdx.x;

    for (int i = 0; i < 32; i++) {
        int idx = tid + i * 256;              // (k, n): n contiguous -> coalesced
        int k = idx >> 7, n = idx & 127;
        float w = W[(size_t)(k0 + k) * DD + n0 + n];
        int slab = k >> 4, klo = k & 15;
        *(__half*)(csm + slab * 6144 + n * 48 + ((klo & 7) << 1) + ((klo >> 3) << 4)) =
            __float2half_rn(w);
    }
    __syncthreads();

    const int w = tid >> 5, lane = tid & 31;   // warp w -> n16 block w
#pragma unroll
    for (int s = 0; s < 4; s++) {
        unsigned bfr[4];
        unsigned addr = cb + s * 6144 +
            (unsigned)((w * 16 + ((lane >> 4) << 3) + (lane & 7)) * 48 +
                       (((lane >> 3) & 1) << 4));
        ldsm_x4(bfr, addr);
        uint4 o4; o4.x = bfr[0]; o4.y = bfr[1]; o4.z = bfr[2]; o4.w = bfr[3];
        g_wF[(((size_t)z * 64 + (n0 >> 4) + w) * 64 + (k0 >> 4) + s) * 32 + lane] = o4;
    }
}

// ---------------------------------------------------------------------------
// fp16 tensor-core GEMM, zero shared memory: C tile 128x128, 256 threads
// (8 warps of m64 x n32). Both A and B are pre-built ldmatrix fragments in
// global (L1/L2 resident); pure LDG.128 + HMMA; no barriers; warps free-run.
// ---------------------------------------------------------------------------
// MODE 0: QKV (z = blockIdx.z; q scaled; head-scatter epilogue, fp16 out)
// MODE 1: out projection (fp32 out + bias)
template<int MODE>
__global__ void __launch_bounds__(256, 2) hgemm(
    const float* __restrict__ biasA, const float* __restrict__ biasB,
    const float* __restrict__ biasC, float* __restrict__ outp)
{
    const int z = (MODE == 0) ? blockIdx.z : 3;
    const float* bias = (MODE == 0) ? ((z == 0) ? biasA : (z == 1) ? biasB : biasC)
                                    : biasA;
    const float scale = (MODE == 0 && z == 0) ? QSCALE : 1.0f;

    const int t = threadIdx.x;
    const int bm = blockIdx.y << 7;
    const int bn = blockIdx.x << 7;
    const int wid = t >> 5, lane = t & 31;
    const int wm = (wid & 1) << 6;       // warp m offset
    const int wn = (wid >> 1) << 5;      // warp n offset

    float acc[4][4][4];
#pragma unroll
    for (int i = 0; i < 4; i++)
#pragma unroll
        for (int j = 0; j < 4; j++)
#pragma unroll
            for (int r = 0; r < 4; r++) acc[i][j][r] = 0.f;

    // fragment pointers (advance by 2 k16 blocks per iteration)
    const uint4* aP  = g_aF + ((size_t)((bm + wm) >> 4) * 64) * 32 + lane;
    const uint4* b0p = g_wF + (((size_t)z * 64 + (bn >> 4) + (wn >> 4)) * 64) * 32 + lane;
    const uint4* b1p = b0p + 64 * 32;    // second n16 block

    const int NIT = DD / 32;   // 32 iterations of BK=32
    for (int it = 0; it < NIT; ++it) {
        // load this iteration's fragments (scoreboard overlaps across warps)
        uint4 a[8];            // [i m16][s ks]
#pragma unroll
        for (int i = 0; i < 4; i++) {
            a[2 * i]     = aP[(size_t)i * 64 * 32];
            a[2 * i + 1] = aP[(size_t)i * 64 * 32 + 32];
        }
        uint4 b[4];            // [s][nb]
        b[0] = b0p[0];  b[1] = b1p[0];
        b[2] = b0p[32]; b[3] = b1p[32];

#pragma unroll
        for (int s = 0; s < 2; s++) {
            unsigned bfr[8];
            *(uint4*)(bfr)     = b[s * 2];
            *(uint4*)(bfr + 4) = b[s * 2 + 1];
#pragma unroll
            for (int i = 0; i < 4; i++) {
                const unsigned* afr = (const unsigned*)&a[2 * i + s];
#pragma unroll
                for (int j = 0; j < 4; j++)
                    mma_f16(acc[i][j], afr, bfr + 2 * j);
            }
        }
        aP  += 2 * 32;
        b0p += 2 * 32;
        b1p += 2 * 32;
    }

    // epilogue
    const int gg = lane >> 2, tg = lane & 3;
#pragma unroll
    for (int i = 0; i < 4; i++) {
#pragma unroll
        for (int j = 0; j < 4; j++) {
            const int row = bm + wm + 16 * i + gg;
            const int col = bn + wn + 8 * j + 2 * tg;
            float v00 = (acc[i][j][0] + bias[col])     * scale;
            float v01 = (acc[i][j][1] + bias[col + 1]) * scale;
            float v10 = (acc[i][j][2] + bias[col])     * scale;
            float v11 = (acc[i][j][3] + bias[col + 1]) * scale;
            if (MODE == 0) {
                const int head = col >> 6, d = col & 63;
                const int b0_ = row >> 11, t0_ = row & 2047;
                const int t1_ = (row + 8) & 2047;      // row+8 stays in same b
                const int bh_ = b0_ * 16 + head;
                if (z == 2) {
                    // vT: [bh][d][t]
                    size_t r0 = ((size_t)bh_ * 64 + d) * 2048;
                    size_t r1 = ((size_t)bh_ * 64 + d + 1) * 2048;
                    g_vTf[r0 + t0_] = __float2half_rn(v00);
                    g_vTf[r1 + t0_] = __float2half_rn(v01);
                    g_vTf[r0 + t1_] = __float2half_rn(v10);
                    g_vTf[r1 + t1_] = __float2half_rn(v11);
                } else {
                    __half* dst = (z == 0) ? g_qf : g_kf;
                    size_t o0 = ((size_t)bh_ * 2048 + t0_) * 64 + d;
                    size_t o1 = ((size_t)bh_ * 2048 + t1_) * 64 + d;
                    *(unsigned*)(dst + o0) = pack_h2(v00, v01);
                    *(unsigned*)(dst + o1) = pack_h2(v10, v11);
                }
            } else {
                outp[(size_t)row * DD + col]           = v00;
                outp[(size_t)row * DD + col + 1]       = v01;
                outp[(size_t)(row + 8) * DD + col]     = v10;
                outp[(size_t)(row + 8) * DD + col + 1] = v11;
            }
        }
    }
}

// ---------------------------------------------------------------------------
// fp16 tensor-core BD3LM attention (unchanged from R13 — 82.5us)
// ---------------------------------------------------------------------------
#define AT_PITCH  144
#define AT_ARR    (64 * AT_PITCH)     // 9216
#define AT_BUF    (2 * AT_ARR)        // 18432 (K, V)
#define AT_SMEM   (3 * AT_BUF)        // 55296

__global__ void __launch_bounds__(128, 4) attn_mma()
{
    extern __shared__ __align__(16) char dsm[];
    const unsigned sb = (unsigned)__cvta_generic_to_shared(dsm);

    const int bi = blockIdx.x;
    const int qt = (bi & 1) ? (31 - (bi >> 1)) : (15 - (bi >> 1));
    const int bh = blockIdx.y;
    const int qt0 = qt << 6;
    const int tid = threadIdx.x;
    const int lane = tid & 31, warp = tid >> 5;
    const int wm = warp << 4;
    const int g = lane >> 2, tq = lane & 3;

#pragma unroll
    for (int i = 0; i < 4; i++) {
        int idx = tid + (i << 7);
        int r = idx >> 3, c = idx & 7;
        cp16(sb + r * AT_PITCH + c * 16,
             g_qf + ((size_t)bh * 2048 + qt0 + r) * 64 + c * 8);
    }
    CP_COMMIT();
    CP_WAIT_0();
    __syncthreads();

    unsigned qf[4][4];
    const unsigned a_off = (unsigned)((wm + (lane & 15)) * AT_PITCH + ((lane >> 4) << 4));
#pragma unroll
    for (int c = 0; c < 4; c++)
        ldsm_x4(qf[c], sb + a_off + c * 32);
    __syncthreads();

    float o[8][4];
#pragma unroll
    for (int j = 0; j < 8; j++)
#pragma unroll
        for (int k = 0; k < 4; k++) o[j][k] = 0.f;
    float osum[4] = {0.f, 0.f, 0.f, 0.f};   // all-ones column: becomes l
    float m0 = -1e30f, m1 = -1e30f;

    const bool is_x0 = (qt >= 16);
    const int nfull  = is_x0 ? (qt - 16) : qt;
    const int ntiles = nfull + (is_x0 ? 1 : 2);

    auto tile_of = [&](int it, int& s, int& mode) {
        if (it < nfull)        { s = 1024 + (it << 6); mode = 0; }
        else if (is_x0)        { s = qt0;              mode = 1; }
        else if (it == nfull)  { s = 1024 + qt0;       mode = 2; }
        else                   { s = qt0;              mode = 3; }
    };

    auto prefetch = [&](int s, int buf) {
        unsigned dstb = sb + buf * AT_BUF;
#pragma unroll
        for (int i = 0; i < 8; i++) {
            int idx = tid + (i << 7);
            int arr = idx >> 9, rem = idx & 511;
            int r = rem >> 3, c = rem & 7;
            const __half* src = (arr == 0)
                ? g_kf  + ((size_t)bh * 2048 + s + r) * 64 + c * 8
                : g_vTf + ((size_t)bh * 64 + r) * 2048 + s + c * 8;
            cp16(dstb + arr * AT_ARR + r * AT_PITCH + c * 16, src);
        }
    };

    {
        int s0, md; tile_of(0, s0, md);
        prefetch(s0, 0);
        CP_COMMIT();
        if (ntiles > 1) { int s1; tile_of(1, s1, md); prefetch(s1, 1); }
        CP_COMMIT();
    }

    const unsigned b_off = (unsigned)((((lane >> 4) << 3) + (lane & 7)) * AT_PITCH +
                                      (((lane >> 3) & 1) << 4));
    const unsigned onesb[2] = {0x3C003C00u, 0x3C003C00u};   // fp16 1.0 x4

    for (int it = 0; it < ntiles; ++it) {
        int s_, mode; tile_of(it, s_, mode);
        if (it < ntiles - 1) { CP_WAIT_1(); } else { CP_WAIT_0(); }
        __syncthreads();

        const unsigned base = sb + (it % 3) * AT_BUF;

        // ---- S = Q K^T ----
        float sc[8][4];
#pragma unroll
        for (int j = 0; j < 8; j++)
#pragma unroll
            for (int k = 0; k < 4; k++) sc[j][k] = 0.f;

#pragma unroll
        for (int c = 0; c < 4; c++) {
#pragma unroll
            for (int p = 0; p < 4; p++) {
                unsigned kb[4];
                ldsm_x4(kb, base + (p << 4) * AT_PITCH + b_off + c * 32);
                mma_f16(sc[2 * p],     qf[c], kb);
                mma_f16(sc[2 * p + 1], qf[c], kb + 2);
            }
        }

        // ---- mask (boundary tiles only): block index = idx>>2 ----
        if (mode) {
#pragma unroll
            for (int j = 0; j < 8; j++)
#pragma unroll
                for (int k = 0; k < 4; k++) {
                    int r = wm + g + ((k >> 1) << 3);
                    int c = (j << 3) + (tq << 1) + (k & 1);
                    int r2 = r >> 2, c2 = c >> 2;
                    bool ok = (mode == 1) ? (c2 <= r2) :
                              (mode == 2) ? (c2 <  r2) : (c2 == r2);
                    if (!ok) sc[j][k] = -1e30f;
                }
        }

        // ---- online softmax: max (fp32) then fp16x2 exp -> P fragments ----
        float t0 = -1e30f, t1 = -1e30f;
#pragma unroll
        for (int j = 0; j < 8; j++) {
            t0 = fmaxf(t0, fmaxf(sc[j][0], sc[j][1]));
            t1 = fmaxf(t1, fmaxf(sc[j][2], sc[j][3]));
        }
        t0 = fmaxf(t0, __shfl_xor_sync(0xffffffffu, t0, 1));
        t0 = fmaxf(t0, __shfl_xor_sync(0xffffffffu, t0, 2));
        t1 = fmaxf(t1, __shfl_xor_sync(0xffffffffu, t1, 1));
        t1 = fmaxf(t1, __shfl_xor_sync(0xffffffffu, t1, 2));
        const float mn0 = fmaxf(m0, t0), mn1 = fmaxf(m1, t1);
        const float r0 = ex2(m0 - mn0), r1 = ex2(m1 - mn1);
        m0 = mn0; m1 = mn1;

        unsigned ph[8], pl[8];   // P fp16x2: rows g / g+8
#pragma unroll
        for (int j = 0; j < 8; j++) {
            ph[j] = h2ex2(pack_h2(sc[j][0] - mn0, sc[j][1] - mn0));
            pl[j] = h2ex2(pack_h2(sc[j][2] - mn1, sc[j][3] - mn1));
        }

        // rescale accumulators (osum follows the same recurrence -> final l)
#pragma unroll
        for (int j = 0; j < 8; j++) {
            o[j][0] *= r0; o[j][1] *= r0;
            o[j][2] *= r1; o[j][3] *= r1;
        }
        osum[0] *= r0; osum[1] *= r0;
        osum[2] *= r1; osum[3] *= r1;

        // ---- O += P V ; osum += P @ ones ----
#pragma unroll
        for (int c = 0; c < 4; c++) {
            unsigned pf[4];
            pf[0] = ph[2 * c];     pf[1] = pl[2 * c];
            pf[2] = ph[2 * c + 1]; pf[3] = pl[2 * c + 1];
            mma_f16(osum, pf, onesb);
#pragma unroll
            for (int p = 0; p < 4; p++) {
                unsigned vb[4];
                ldsm_x4(vb, base + AT_ARR + (p << 4) * AT_PITCH + b_off + c * 32);
                mma_f16(o[2 * p],     pf, vb);
                mma_f16(o[2 * p + 1], pf, vb + 2);
            }
        }

        if (it + 2 < ntiles) {
            int sn, mn; tile_of(it + 2, sn, mn);
            prefetch(sn, (it + 2) % 3);
            CP_COMMIT();
        }
    }

    // ---- epilogue: normalize by osum (== l), store ctx fp16 ----
    const float inv0 = 1.f / osum[0], inv1 = 1.f / osum[2];
    const int b_ = bh >> 4, h_ = bh & 15;
    const int row0 = qt0 + wm + g;
    __half* c0 = g_cf + ((size_t)b_ * 2048 + row0) * 1024 + h_ * 64 + (tq << 1);
#pragma unroll
    for (int j = 0; j < 8; j++) {
        *(unsigned*)(c0 + (j << 3)) = pack_h2(o[j][0] * inv0, o[j][1] * inv0);
        *(unsigned*)(c0 + 8 * 1024 + (j << 3)) = pack_h2(o[j][2] * inv1, o[j][3] * inv1);
    }
}

// ---------------------------------------------------------------------------

extern "C" void kernel_launch(void* const* d_in, const int* in_sizes, int n_in,
                              void* d_out, int out_size)
{
    const float* x  = (const float*)d_in[0];
    const float* Wq = (const float*)d_in[1];
    const float* bq = (const float*)d_in[2];
    const float* Wk = (const float*)d_in[3];
    const float* bk = (const float*)d_in[4];
    const float* Wv = (const float*)d_in[5];
    const float* bv = (const float*)d_in[6];
    const float* Wo = (const float*)d_in[7];
    const float* bo = (const float*)d_in[8];

    cudaFuncSetAttribute(attn_mma, cudaFuncAttributeMaxDynamicSharedMemorySize, AT_SMEM);

    conv_aF<0><<<dim3(64, 16), 256>>>(x);          // x -> A fragments
    conv_wF<<<dim3(8, 16, 4), 256>>>(Wq, Wk, Wv, Wo);

    hgemm<0><<<dim3(8, 64, 3), 256>>>(bq, bk, bv, nullptr);

    attn_mma<<<dim3(32, 64), 128, AT_SMEM>>>();

    conv_aF<1><<<dim3(64, 16), 256>>>(nullptr);    // ctx -> A fragments
    hgemm<1><<<dim3(8, 64), 256>>>(bo, nullptr, nullptr, (float*)d_out);
}